// round 11
// baseline (speedup 1.0000x reference)
#include <cuda_runtime.h>
#include <cuda_bf16.h>
#include <cstddef>
#include <cstdint>

typedef unsigned long long u64;
typedef unsigned int u32;
typedef __nv_bfloat16 bf16;

#define NCTA 148
#define NTHR 512
#define NSTAGE 5

// smem chunk layout (bytes): A 128x64 hi/lo (rows padded 144B), B 32x64 hi/lo
#define OFF_AL 18432
#define OFF_BH 36864
#define OFF_BL 41472
#define BUFSZ 46080

// ---------------- device scratch ----------------
__device__ float g_Xpre[(size_t)512 * 64 * 3072];  // [t][b][3072]
__device__ float g_H2[(size_t)512 * 64 * 1024];    // [t][b][1024]
__device__ float g_hbuf[2][3][65536];              // fp32 h (parity, layer) [b][n]
__device__ float g_z[3][65536];                    // z gate [b][n]
__device__ __align__(16) bf16 g_hbH[2][3][65536];
__device__ __align__(16) bf16 g_hbL[2][3][65536];
__device__ __align__(16) bf16 g_rhH[3][65536];
__device__ __align__(16) bf16 g_rhL[3][65536];
__device__ __align__(16) bf16 g_WhH[(size_t)3 * 3072 * 1024];  // l0=Wh0, l1/2=Whr
__device__ __align__(16) bf16 g_WhL[(size_t)3 * 3072 * 1024];
__device__ __align__(16) bf16 g_WxH[(size_t)2 * 3072 * 1024];  // Wxr
__device__ __align__(16) bf16 g_WxL[(size_t)2 * 3072 * 1024];
// K-quartile partials, element layout [n*64 + b]
__device__ float g_pA[8][3][2048 * 64];  // zr: slots 0-3 h-path kq, 4-7 x-path kq
__device__ float g_pC[8][3][1024 * 64];  // g:  slots 0-3 x-path kq, 4-7 rh-path kq
__device__ unsigned g_cnt;
__device__ volatile unsigned g_gen;

// ---------------- generic helpers ----------------
__device__ __forceinline__ u64 ffma2(u64 a, u64 b, u64 c) {
    u64 d;
    asm("fma.rn.f32x2 %0, %1, %2, %3;" : "=l"(d) : "l"(a), "l"(b), "l"(c));
    return d;
}
__device__ __forceinline__ float psum(u64 a) {
    float2 f = *reinterpret_cast<float2*>(&a);
    return f.x + f.y;
}
__device__ __forceinline__ float sigm(float x) { return 1.f / (1.f + __expf(-x)); }

__device__ __forceinline__ void gridbar() {
    __syncthreads();
    if (threadIdx.x == 0) {
        unsigned old = g_gen;
        __threadfence();
        if (atomicAdd(&g_cnt, 1u) == NCTA - 1) {
            g_cnt = 0;
            __threadfence();
            g_gen = old + 1;
        } else {
            while (g_gen == old) __nanosleep(32);
            __threadfence();
        }
    }
    __syncthreads();
}

// ---------------- mma / ldmatrix / cp.async primitives ----------------
__device__ __forceinline__ u32 smem_u32(const void* p) {
    u32 a;
    asm("{ .reg .u64 t; cvta.to.shared.u64 t, %1; cvt.u32.u64 %0, t; }" : "=r"(a) : "l"(p));
    return a;
}
__device__ __forceinline__ void mma16816(float* d, const u32* a, const u32* b) {
    asm volatile(
        "mma.sync.aligned.m16n8k16.row.col.f32.bf16.bf16.f32 "
        "{%0,%1,%2,%3}, {%4,%5,%6,%7}, {%8,%9}, {%0,%1,%2,%3};"
        : "+f"(d[0]), "+f"(d[1]), "+f"(d[2]), "+f"(d[3])
        : "r"(a[0]), "r"(a[1]), "r"(a[2]), "r"(a[3]), "r"(b[0]), "r"(b[1]));
}
__device__ __forceinline__ void ldm4(u32& r0, u32& r1, u32& r2, u32& r3, u32 addr) {
    asm volatile("ldmatrix.sync.aligned.m8n8.x4.shared.b16 {%0,%1,%2,%3}, [%4];"
                 : "=r"(r0), "=r"(r1), "=r"(r2), "=r"(r3) : "r"(addr));
}
__device__ __forceinline__ void cpa(u32 dst, const void* src) {
    asm volatile("cp.async.cg.shared.global [%0], [%1], 16;" :: "r"(dst), "l"(src) : "memory");
}
__device__ __forceinline__ void cp_commit() { asm volatile("cp.async.commit_group;" ::: "memory"); }
__device__ __forceinline__ void cp_waitN(int rem) {
    if (rem >= 3) asm volatile("cp.async.wait_group 3;" ::: "memory");
    else if (rem == 2) asm volatile("cp.async.wait_group 2;" ::: "memory");
    else if (rem == 1) asm volatile("cp.async.wait_group 1;" ::: "memory");
    else asm volatile("cp.async.wait_group 0;" ::: "memory");
}

struct Job { const bf16 *AH, *AL, *BH, *BL; float* dst; };

// ---------------- job decode ----------------
// Phase A: 768 jobs. 0-383 zr-h, 384-639 zr-x, 640-767 g-x. All (M=128,N=32,K=256).
__device__ __forceinline__ int jobA_layer(int j) {
    if (j < 384) return j >> 7;
    if (j < 640) return ((j - 384) >> 7) + 1;
    return ((j - 640) >> 6) + 1;
}
__device__ __forceinline__ Job decodeA(int j, int rd) {
    Job jb;
    if (j < 384) {
        int l = j >> 7, r = j & 127, tt = r >> 3, nh = (r >> 2) & 1, kq = r & 3;
        size_t arow = (size_t)l * 3072 + tt * 128;
        jb.AH = g_WhH + arow * 1024 + kq * 256;
        jb.AL = g_WhL + arow * 1024 + kq * 256;
        jb.BH = g_hbH[rd][l] + nh * 32 * 1024 + kq * 256;
        jb.BL = g_hbL[rd][l] + nh * 32 * 1024 + kq * 256;
        jb.dst = &g_pA[kq][l][tt * 128 * 64 + nh * 32];
    } else if (j < 640) {
        int j2 = j - 384;
        int lm = j2 >> 7, r = j2 & 127, tt = r >> 3, nh = (r >> 2) & 1, kq = r & 3;
        size_t arow = (size_t)lm * 3072 + tt * 128;
        jb.AH = g_WxH + arow * 1024 + kq * 256;
        jb.AL = g_WxL + arow * 1024 + kq * 256;
        jb.BH = g_hbH[rd][lm] + nh * 32 * 1024 + kq * 256;
        jb.BL = g_hbL[rd][lm] + nh * 32 * 1024 + kq * 256;
        jb.dst = &g_pA[4 + kq][lm + 1][tt * 128 * 64 + nh * 32];
    } else {
        int j3 = j - 640;
        int lm = j3 >> 6, r = j3 & 63, tt8 = r >> 3, nh = (r >> 2) & 1, kq = r & 3;
        size_t arow = (size_t)lm * 3072 + 2048 + tt8 * 128;
        jb.AH = g_WxH + arow * 1024 + kq * 256;
        jb.AL = g_WxL + arow * 1024 + kq * 256;
        jb.BH = g_hbH[rd][lm] + nh * 32 * 1024 + kq * 256;
        jb.BL = g_hbL[rd][lm] + nh * 32 * 1024 + kq * 256;
        jb.dst = &g_pC[kq][lm + 1][tt8 * 128 * 64 + nh * 32];
    }
    return jb;
}
// Phase C: 192 jobs (g rh-path), layer = j>>6.
__device__ __forceinline__ Job decodeC(int j, int rd) {
    Job jb;
    int l = j >> 6, r = j & 63, tt8 = r >> 3, nh = (r >> 2) & 1, kq = r & 3;
    size_t arow = (size_t)l * 3072 + 2048 + tt8 * 128;
    jb.AH = g_WhH + arow * 1024 + kq * 256;
    jb.AL = g_WhL + arow * 1024 + kq * 256;
    jb.BH = g_rhH[l] + nh * 32 * 1024 + kq * 256;
    jb.BL = g_rhL[l] + nh * 32 * 1024 + kq * 256;
    jb.dst = &g_pC[4 + kq][l][tt8 * 128 * 64 + nh * 32];
    return jb;
}

// issue one K=64 chunk (A 128x64 hi/lo, B 32x64 hi/lo) into smem buffer (512 thr)
__device__ __forceinline__ void issue_chunk(u32 sbuf, const Job& s, int koff, int tid) {
#pragma unroll
    for (int it = 0; it < 2; it++) {
        int idx = tid + NTHR * it;
        int row = idx >> 3, c16 = idx & 7;
        u32 d = sbuf + row * 144 + c16 * 16;
        size_t so = (size_t)row * 1024 + koff + c16 * 8;
        cpa(d, s.AH + so);
        cpa(d + OFF_AL, s.AL + so);
    }
    if (tid < 256) {
        int row = tid >> 3, c16 = tid & 7;
        u32 d = sbuf + OFF_BH + row * 144 + c16 * 16;
        size_t so = (size_t)row * 1024 + koff + c16 * 8;
        cpa(d, s.BH + so);
        cpa(d + (OFF_BL - OFF_BH), s.BL + so);
    }
    cp_commit();
}

// compute one K=64 chunk: 16 warps = 8(M) x 2(N); warp tile m16 x n16
__device__ __forceinline__ void mma_chunk(u32 sbuf, float (&acc)[2][4], int mw, int nw,
                                          int lane) {
    const int arow = ((lane >> 3) & 1) * 8 + (lane & 7);
    const int akk = ((lane >> 4) & 1) * 8;
    const int brow = ((lane >> 4) & 1) * 8 + (lane & 7);
    const int bkk = ((lane >> 3) & 1) * 8;
#pragma unroll
    for (int ks = 0; ks < 4; ks++) {
        int kOff = ks * 16;
        u32 aH[4], aL[4];
        {
            int row = mw * 16 + arow;
            u32 ad = sbuf + row * 144 + (kOff + akk) * 2;
            ldm4(aH[0], aH[1], aH[2], aH[3], ad);
            ldm4(aL[0], aL[1], aL[2], aL[3], ad + OFF_AL);
        }
        u32 bH[2][2], bL[2][2];
        {
            int nrow = nw * 16 + brow;
            u32 bd = sbuf + OFF_BH + nrow * 144 + (kOff + bkk) * 2;
            u32 r0, r1, r2, r3;
            ldm4(r0, r1, r2, r3, bd);
            bH[0][0] = r0; bH[0][1] = r1; bH[1][0] = r2; bH[1][1] = r3;
            ldm4(r0, r1, r2, r3, bd + (OFF_BL - OFF_BH));
            bL[0][0] = r0; bL[0][1] = r1; bL[1][0] = r2; bL[1][1] = r3;
        }
#pragma unroll
        for (int nt = 0; nt < 2; nt++) {
            mma16816(acc[nt], aH, bH[nt]);
            mma16816(acc[nt], aH, bL[nt]);
            mma16816(acc[nt], aL, bH[nt]);
        }
    }
}

__device__ __forceinline__ void zero_acc(float (&acc)[2][4]) {
#pragma unroll
    for (int j = 0; j < 2; j++)
#pragma unroll
        for (int e = 0; e < 4; e++) acc[j][e] = 0.f;
}

// run up to nv jobs (4 chunks each), 5-stage ring, depth-4 prefetch, store partials
__device__ __forceinline__ void run_phase(const int* jl, int nv, bool isA, int rd, u32 sm0,
                                          int tid, int mw, int nw, int lane, int rlo, int cb) {
    if (nv == 0) return;
    float acc[2][4];
    zero_acc(acc);
    const int n = nv * 4;
    for (int j = 0; j < 4 && j < n; j++) {
        Job jb = isA ? decodeA(jl[j >> 2], rd) : decodeC(jl[j >> 2], rd);
        issue_chunk(sm0 + j * BUFSZ, jb, (j & 3) * 64, tid);
    }
    for (int i = 0; i < n; i++) {
        int rem = n - 1 - i;
        cp_waitN(rem < 3 ? rem : 3);
        __syncthreads();
        int nx = i + 4;
        if (nx < n) {
            Job jb = isA ? decodeA(jl[nx >> 2], rd) : decodeC(jl[nx >> 2], rd);
            issue_chunk(sm0 + (nx % NSTAGE) * BUFSZ, jb, (nx & 3) * 64, tid);
        }
        mma_chunk(sm0 + (i % NSTAGE) * BUFSZ, acc, mw, nw, lane);
        if ((i & 3) == 3) {
            Job jb = isA ? decodeA(jl[i >> 2], rd) : decodeC(jl[i >> 2], rd);
#pragma unroll
            for (int half = 0; half < 2; half++) {
                int mrow = mw * 16 + half * 8 + rlo;
#pragma unroll
                for (int nt = 0; nt < 2; nt++)
#pragma unroll
                    for (int e = 0; e < 2; e++) {
                        int bcol = nw * 16 + nt * 8 + cb + e;
                        jb.dst[mrow * 64 + bcol] = acc[nt][half * 2 + e];
                    }
            }
            zero_acc(acc);
        }
    }
    __syncthreads();
}

// ---------------- SIMT f32x2 GEMM (xpre / yout) ----------------
__device__ __forceinline__ void gemm_tile(const float* __restrict__ A, int lda,
                                          const float* __restrict__ W, int ldw,
                                          float* __restrict__ C, int cld,
                                          const float* __restrict__ bias, int nch,
                                          u64* __restrict__ Sm) {
    const int tid = threadIdx.x, tx = tid & 15, ty = tid >> 4;
    u64 acc[8][8];
#pragma unroll
    for (int i = 0; i < 8; i++)
#pragma unroll
        for (int j = 0; j < 8; j++) acc[i][j] = 0ull;
    u64 rA[8], rB[16];
#pragma unroll
    for (int it = 0; it < 8; it++) {
        int idx = tid + 128 * it, row = idx >> 4, k8 = idx & 15;
        rA[it] = *reinterpret_cast<const u64*>(A + (size_t)row * lda + (k8 << 1));
    }
#pragma unroll
    for (int it = 0; it < 16; it++) {
        int idx = tid + 128 * it, row = idx >> 4, k8 = idx & 15;
        rB[it] = *reinterpret_cast<const u64*>(W + (size_t)row * ldw + (k8 << 1));
    }
    for (int c = 0; c < nch; c++) {
        u64* Ab = Sm + (c & 1) * 3072;
        u64* Bb = Ab + 1024;
#pragma unroll
        for (int it = 0; it < 8; it++) {
            int idx = tid + 128 * it, row = idx >> 4, k8 = idx & 15;
            Ab[(row << 4) + (k8 ^ ((row >> 3) & 15))] = rA[it];
        }
#pragma unroll
        for (int it = 0; it < 16; it++) {
            int idx = tid + 128 * it, row = idx >> 4, k8 = idx & 15;
            Bb[(row << 4) + (k8 ^ ((row >> 3) & 15))] = rB[it];
        }
        __syncthreads();
        if (c + 1 < nch) {
            const float* A2 = A + (c + 1) * 32;
            const float* W2 = W + (c + 1) * 32;
#pragma unroll
            for (int it = 0; it < 8; it++) {
                int idx = tid + 128 * it, row = idx >> 4, k8 = idx & 15;
                rA[it] = *reinterpret_cast<const u64*>(A2 + (size_t)row * lda + (k8 << 1));
            }
#pragma unroll
            for (int it = 0; it < 16; it++) {
                int idx = tid + 128 * it, row = idx >> 4, k8 = idx & 15;
                rB[it] = *reinterpret_cast<const u64*>(W2 + (size_t)row * ldw + (k8 << 1));
            }
        }
#pragma unroll
        for (int k8 = 0; k8 < 16; k8++) {
            u64 a2[8], b2[8];
#pragma unroll
            for (int i = 0; i < 8; i++) a2[i] = Ab[((ty * 8 + i) << 4) + (k8 ^ ty)];
#pragma unroll
            for (int j = 0; j < 8; j++) b2[j] = Bb[((tx * 8 + j) << 4) + (k8 ^ tx)];
#pragma unroll
            for (int i = 0; i < 8; i++)
#pragma unroll
                for (int j = 0; j < 8; j++) acc[i][j] = ffma2(a2[i], b2[j], acc[i][j]);
        }
    }
#pragma unroll
    for (int i = 0; i < 8; i++)
#pragma unroll
        for (int j = 0; j < 8; j++) {
            float v = psum(acc[i][j]);
            if (bias) v += bias[tx * 8 + j];
            C[(size_t)(ty * 8 + i) * cld + tx * 8 + j] = v;
        }
    __syncthreads();
}

// ---------------- kernels ----------------
__global__ void k_pad() {}

__global__ void k_conv(const float* __restrict__ Wh0, const float* __restrict__ Whr,
                       const float* __restrict__ Wxr) {
    const size_t NWH = (size_t)3 * 3072 * 1024;
    const size_t NTOT = (size_t)5 * 3072 * 1024;
    for (size_t i = (size_t)blockIdx.x * blockDim.x + threadIdx.x; i < NTOT;
         i += (size_t)gridDim.x * blockDim.x) {
        float w;
        bf16 *H, *L;
        size_t o;
        if (i < NWH) {
            o = i;
            w = (i < (size_t)3072 * 1024) ? Wh0[i] : Whr[i - (size_t)3072 * 1024];
            H = g_WhH; L = g_WhL;
        } else {
            o = i - NWH;
            w = Wxr[o];
            H = g_WxH; L = g_WxL;
        }
        bf16 h = __float2bfloat16_rn(w);
        H[o] = h;
        L[o] = __float2bfloat16_rn(w - __bfloat162float(h));
    }
}

__global__ __launch_bounds__(128, 2) void k_xpre(const float* __restrict__ x,
                                                 const float* __restrict__ Wx0) {
    __shared__ __align__(16) u64 Sm[6144];
    int n0 = blockIdx.x * 128, s = blockIdx.y;
    gemm_tile(x + (size_t)s * 128, 512 * 128, Wx0 + (size_t)n0 * 128, 128,
              g_Xpre + (size_t)s * 64 * 3072 + n0, 3072, nullptr, 4, Sm);
}

// persistent wavefront GRU: balanced 4-phase schedule, mma.sync bf16-split
__global__ __launch_bounds__(NTHR) void k_gru(const float* __restrict__ bh0,
                                              const float* __restrict__ bhr) {
    extern __shared__ __align__(16) char dsm[];
    const u32 sm0 = smem_u32(dsm);
    const int tid = threadIdx.x, wid = tid >> 5, lane = tid & 31;
    const int mw = wid >> 1, nw = wid & 1;  // 8 M-warps x 2 N-warps
    const int cta = blockIdx.x;
    const int gtid = cta * NTHR + tid;
    const int rlo = lane >> 2, cb = (lane & 3) * 2;

    for (int i = gtid; i < 2 * 3 * 65536; i += NCTA * NTHR) {
        (&g_hbuf[0][0][0])[i] = 0.f;
        (&g_hbH[0][0][0])[i] = __float2bfloat16_rn(0.f);
        (&g_hbL[0][0][0])[i] = __float2bfloat16_rn(0.f);
    }
    gridbar();

    int jl[6];

    for (int w = 0; w < 514; ++w) {
        const int rd = w & 1, wb = rd ^ 1;

        // ======== Phase A: all zr + g-x GEMM jobs, K-quartile partials ========
        int nv = 0;
#pragma unroll
        for (int k = 0; k < 6; k++) {
            int j = cta + k * NCTA;
            if (j < 768) {
                int l = jobA_layer(j);
                int t = w - l;
                if (t >= 0 && t < 512) jl[nv++] = j;
            }
        }
        run_phase(jl, nv, true, rd, sm0, tid, mw, nw, lane, rlo, cb);
        gridbar();

        // ======== Epi B: combine partials -> z, rh ========
        for (int idx = gtid; idx < 3 * 2048 * 64; idx += NCTA * NTHR) {
            int l = idx / (2048 * 64);
            int rem = idx - l * (2048 * 64);
            int t = w - l;
            if (t < 0 || t >= 512) continue;
            int n = rem >> 6, b = rem & 63;
            float v = (l == 0) ? bh0[n] : bhr[(l - 1) * 3072 + n];
            v += g_pA[0][l][rem] + g_pA[1][l][rem] + g_pA[2][l][rem] + g_pA[3][l][rem];
            if (l > 0)
                v += g_pA[4][l][rem] + g_pA[5][l][rem] + g_pA[6][l][rem] + g_pA[7][l][rem];
            else
                v += g_Xpre[((size_t)t * 64 + b) * 3072 + n];
            float s = sigm(v);
            if (n < 1024) {
                g_z[l][b * 1024 + n] = s;
            } else {
                int nn = n - 1024;
                float rv = s * g_hbuf[rd][l][b * 1024 + nn];
                bf16 hi = __float2bfloat16_rn(rv);
                g_rhH[l][b * 1024 + nn] = hi;
                g_rhL[l][b * 1024 + nn] = __float2bfloat16_rn(rv - __bfloat162float(hi));
            }
        }
        gridbar();

        // ======== Phase C: g rh-path jobs ========
        nv = 0;
#pragma unroll
        for (int k = 0; k < 2; k++) {
            int j = cta + k * NCTA;
            if (j < 192) {
                int l = j >> 6;
                int t = w - l;
                if (t >= 0 && t < 512) jl[nv++] = j;
            }
        }
        run_phase(jl, nv, false, rd, sm0, tid, mw, nw, lane, rlo, cb);
        gridbar();

        // ======== Epi D: combine -> g gate, h update ========
        for (int idx = gtid; idx < 3 * 1024 * 64; idx += NCTA * NTHR) {
            int l = idx >> 16;
            int rem = idx & 65535;
            int t = w - l;
            if (t < 0 || t >= 512) continue;
            int n = rem >> 6, b = rem & 63;
            float v = (l == 0) ? bh0[2048 + n] : bhr[(l - 1) * 3072 + 2048 + n];
            v += g_pC[4][l][rem] + g_pC[5][l][rem] + g_pC[6][l][rem] + g_pC[7][l][rem];
            if (l > 0)
                v += g_pC[0][l][rem] + g_pC[1][l][rem] + g_pC[2][l][rem] + g_pC[3][l][rem];
            else
                v += g_Xpre[((size_t)t * 64 + b) * 3072 + 2048 + n];
            float gg = tanhf(v);
            float z = g_z[l][b * 1024 + n];
            float hp = g_hbuf[rd][l][b * 1024 + n];
            float hn = z * hp + (1.f - z) * gg;
            g_hbuf[wb][l][b * 1024 + n] = hn;
            bf16 hi = __float2bfloat16_rn(hn);
            g_hbH[wb][l][b * 1024 + n] = hi;
            g_hbL[wb][l][b * 1024 + n] = __float2bfloat16_rn(hn - __bfloat162float(hi));
            if (l == 2) g_H2[((size_t)t * 64 + b) * 1024 + n] = hn;
        }
        gridbar();
    }
}

__global__ __launch_bounds__(128, 2) void k_yout(const float* __restrict__ Wout,
                                                 const float* __restrict__ bout,
                                                 float* __restrict__ out) {
    __shared__ __align__(16) u64 Sm[6144];
    int s = blockIdx.x;
    gemm_tile(g_H2 + (size_t)s * 64 * 1024, 1024, Wout, 1024,
              out + (size_t)s * 128, 512 * 128, bout, 32, Sm);
}

__global__ void k_hout(float* __restrict__ out) {
    int i = blockIdx.x * 256 + threadIdx.x;
    if (i >= 3 * 64 * 1024) return;
    int l = i / (64 * 1024);
    int r = i % (64 * 1024);
    int b = r / 1024, n = r % 1024;
    out[(size_t)64 * 512 * 128 + ((size_t)b * 3 + l) * 1024 + n] = g_hbuf[l & 1][l][r];
}

extern "C" void kernel_launch(void* const* d_in, const int* in_sizes, int n_in,
                              void* d_out, int out_size) {
    const float* x = (const float*)d_in[0];
    const float* Wx0 = (const float*)d_in[1];
    const float* Wh0 = (const float*)d_in[2];
    const float* bh0 = (const float*)d_in[3];
    const float* Wxr = (const float*)d_in[4];
    const float* Whr = (const float*)d_in[5];
    const float* bhr = (const float*)d_in[6];
    const float* Wout = (const float*)d_in[7];
    const float* bout = (const float*)d_in[8];
    float* out = (float*)d_out;

    cudaFuncSetAttribute(k_gru, cudaFuncAttributeMaxDynamicSharedMemorySize, NSTAGE * BUFSZ);

    k_pad<<<1, 32>>>();
    k_conv<<<2048, 256>>>(Wh0, Whr, Wxr);
    k_xpre<<<dim3(24, 512), 128>>>(x, Wx0);
    k_gru<<<NCTA, NTHR, NSTAGE * BUFSZ>>>(bh0, bhr);  // my 4th launch -> ncu -s 5
    k_yout<<<512, 128>>>(Wout, bout, out);
    k_hout<<<(3 * 64 * 1024 + 255) / 256, 256>>>(out);
}

// round 12
// speedup vs baseline: 1.2435x; 1.2435x over previous
#include <cuda_runtime.h>
#include <cuda_bf16.h>
#include <cstddef>
#include <cstdint>

typedef unsigned long long u64;
typedef unsigned int u32;
typedef __nv_bfloat16 bf16;

#define NCTA 148
#define NTHR 512
#define NSTAGE 5

// smem chunk layout (bytes): A 128x64 hi/lo (rows padded 144B), B 32x64 hi/lo
#define OFF_AL 18432
#define OFF_BH 36864
#define OFF_BL 41472
#define BUFSZ 46080

// ---------------- device scratch ----------------
__device__ float g_Xpre[(size_t)512 * 64 * 3072];  // [t][b][3072]
__device__ float g_H2[(size_t)512 * 64 * 1024];    // [t][b][1024]
__device__ float g_hbuf[2][3][65536];              // fp32 h (parity, layer) [b][n]
__device__ __align__(16) bf16 g_hbH[2][3][65536];
__device__ __align__(16) bf16 g_hbL[2][3][65536];
__device__ __align__(16) bf16 g_rhH[3][65536];
__device__ __align__(16) bf16 g_rhL[3][65536];
__device__ __align__(16) bf16 g_WhH[(size_t)3 * 3072 * 1024];  // l0=Wh0, l1/2=Whr
__device__ __align__(16) bf16 g_WhL[(size_t)3 * 3072 * 1024];
__device__ __align__(16) bf16 g_WxH[(size_t)2 * 3072 * 1024];  // Wxr
__device__ __align__(16) bf16 g_WxL[(size_t)2 * 3072 * 1024];
// K-half partials, element layout [n*64 + b]
__device__ float g_pA[4][3][2048 * 64];  // zr: 0-1 h-path kq, 2-3 x-path kq
__device__ float g_pC[4][3][1024 * 64];  // g:  0-1 x-path kq, 2-3 rh-path kq
__device__ unsigned g_cnt;
__device__ volatile unsigned g_gen;

// ---------------- generic helpers ----------------
__device__ __forceinline__ u64 ffma2(u64 a, u64 b, u64 c) {
    u64 d;
    asm("fma.rn.f32x2 %0, %1, %2, %3;" : "=l"(d) : "l"(a), "l"(b), "l"(c));
    return d;
}
__device__ __forceinline__ float psum(u64 a) {
    float2 f = *reinterpret_cast<float2*>(&a);
    return f.x + f.y;
}
__device__ __forceinline__ float sigm(float x) { return 1.f / (1.f + __expf(-x)); }

__device__ __forceinline__ void gridbar() {
    __syncthreads();
    if (threadIdx.x == 0) {
        unsigned old = g_gen;
        __threadfence();
        if (atomicAdd(&g_cnt, 1u) == NCTA - 1) {
            g_cnt = 0;
            __threadfence();
            g_gen = old + 1;
        } else {
            while (g_gen == old) __nanosleep(32);
            __threadfence();
        }
    }
    __syncthreads();
}

// ---------------- mma / ldmatrix / cp.async primitives ----------------
__device__ __forceinline__ u32 smem_u32(const void* p) {
    u32 a;
    asm("{ .reg .u64 t; cvta.to.shared.u64 t, %1; cvt.u32.u64 %0, t; }" : "=r"(a) : "l"(p));
    return a;
}
__device__ __forceinline__ void mma16816(float* d, const u32* a, const u32* b) {
    asm volatile(
        "mma.sync.aligned.m16n8k16.row.col.f32.bf16.bf16.f32 "
        "{%0,%1,%2,%3}, {%4,%5,%6,%7}, {%8,%9}, {%0,%1,%2,%3};"
        : "+f"(d[0]), "+f"(d[1]), "+f"(d[2]), "+f"(d[3])
        : "r"(a[0]), "r"(a[1]), "r"(a[2]), "r"(a[3]), "r"(b[0]), "r"(b[1]));
}
__device__ __forceinline__ void ldm4(u32& r0, u32& r1, u32& r2, u32& r3, u32 addr) {
    asm volatile("ldmatrix.sync.aligned.m8n8.x4.shared.b16 {%0,%1,%2,%3}, [%4];"
                 : "=r"(r0), "=r"(r1), "=r"(r2), "=r"(r3) : "r"(addr));
}
__device__ __forceinline__ void cpa(u32 dst, const void* src) {
    asm volatile("cp.async.cg.shared.global [%0], [%1], 16;" :: "r"(dst), "l"(src) : "memory");
}
__device__ __forceinline__ void cp_commit() { asm volatile("cp.async.commit_group;" ::: "memory"); }
__device__ __forceinline__ void cp_waitN(int rem) {
    if (rem >= 3) asm volatile("cp.async.wait_group 3;" ::: "memory");
    else if (rem == 2) asm volatile("cp.async.wait_group 2;" ::: "memory");
    else if (rem == 1) asm volatile("cp.async.wait_group 1;" ::: "memory");
    else asm volatile("cp.async.wait_group 0;" ::: "memory");
}

struct Job { const bf16 *AH, *AL, *BH, *BL; float* dst; };

__device__ __forceinline__ Job jsel(const Job ja[3], int k) {
    Job r = ja[0];
    if (k == 1) r = ja[1];
    if (k == 2) r = ja[2];
    return r;
}

// issue one K=64 chunk (A 128x64 hi/lo, B 32x64 hi/lo) into smem buffer (512 thr)
__device__ __forceinline__ void issue_chunk(u32 sbuf, const Job& s, int koff, int tid) {
#pragma unroll
    for (int it = 0; it < 2; it++) {
        int idx = tid + NTHR * it;
        int row = idx >> 3, c16 = idx & 7;
        u32 d = sbuf + row * 144 + c16 * 16;
        size_t so = (size_t)row * 1024 + koff + c16 * 8;
        cpa(d, s.AH + so);
        cpa(d + OFF_AL, s.AL + so);
    }
    if (tid < 256) {
        int row = tid >> 3, c16 = tid & 7;
        u32 d = sbuf + OFF_BH + row * 144 + c16 * 16;
        size_t so = (size_t)row * 1024 + koff + c16 * 8;
        cpa(d, s.BH + so);
        cpa(d + (OFF_BL - OFF_BH), s.BL + so);
    }
    cp_commit();
}

// compute one K=64 chunk: 16 warps = 8(M) x 2(N); warp tile m16 x n16
__device__ __forceinline__ void mma_chunk(u32 sbuf, float (&acc)[2][4], int mw, int nw,
                                          int lane) {
    const int arow = ((lane >> 3) & 1) * 8 + (lane & 7);
    const int akk = ((lane >> 4) & 1) * 8;
    const int brow = ((lane >> 4) & 1) * 8 + (lane & 7);
    const int bkk = ((lane >> 3) & 1) * 8;
#pragma unroll
    for (int ks = 0; ks < 4; ks++) {
        int kOff = ks * 16;
        u32 aH[4], aL[4];
        {
            int row = mw * 16 + arow;
            u32 ad = sbuf + row * 144 + (kOff + akk) * 2;
            ldm4(aH[0], aH[1], aH[2], aH[3], ad);
            ldm4(aL[0], aL[1], aL[2], aL[3], ad + OFF_AL);
        }
        u32 bH[2][2], bL[2][2];
        {
            int nrow = nw * 16 + brow;
            u32 bd = sbuf + OFF_BH + nrow * 144 + (kOff + bkk) * 2;
            u32 r0, r1, r2, r3;
            ldm4(r0, r1, r2, r3, bd);
            bH[0][0] = r0; bH[0][1] = r1; bH[1][0] = r2; bH[1][1] = r3;
            ldm4(r0, r1, r2, r3, bd + (OFF_BL - OFF_BH));
            bL[0][0] = r0; bL[0][1] = r1; bL[1][0] = r2; bL[1][1] = r3;
        }
#pragma unroll
        for (int nt = 0; nt < 2; nt++) {
            mma16816(acc[nt], aH, bH[nt]);
            mma16816(acc[nt], aH, bL[nt]);
            mma16816(acc[nt], aL, bH[nt]);
        }
    }
}

__device__ __forceinline__ void zero_acc(float (&acc)[2][4]) {
#pragma unroll
    for (int j = 0; j < 2; j++)
#pragma unroll
        for (int e = 0; e < 4; e++) acc[j][e] = 0.f;
}

// run nv jobs x 8 chunks, 5-stage ring, depth-4 prefetch, store fp32 partials
__device__ __forceinline__ void run_jobs(const Job ja[3], int nv, u32 sm0, int tid, int mw,
                                         int nw, int lane, int rlo, int cb) {
    if (nv == 0) return;
    float acc[2][4];
    zero_acc(acc);
    const int n = nv * 8;
#pragma unroll
    for (int j = 0; j < 4; j++)
        if (j < n) issue_chunk(sm0 + j * BUFSZ, jsel(ja, j >> 3), (j & 7) * 64, tid);
    for (int i = 0; i < n; i++) {
        int rem = n - 1 - i;
        cp_waitN(rem < 3 ? rem : 3);
        __syncthreads();
        int nx = i + 4;
        if (nx < n)
            issue_chunk(sm0 + (nx % NSTAGE) * BUFSZ, jsel(ja, nx >> 3), (nx & 7) * 64, tid);
        mma_chunk(sm0 + (i % NSTAGE) * BUFSZ, acc, mw, nw, lane);
        if ((i & 7) == 7) {
            float* dst = jsel(ja, i >> 3).dst;
#pragma unroll
            for (int half = 0; half < 2; half++) {
                int mrow = mw * 16 + half * 8 + rlo;
#pragma unroll
                for (int nt = 0; nt < 2; nt++)
#pragma unroll
                    for (int e = 0; e < 2; e++)
                        dst[mrow * 64 + nw * 16 + nt * 8 + cb + e] = acc[nt][half * 2 + e];
            }
            zero_acc(acc);
        }
    }
    __syncthreads();
}

// ---------------- SIMT f32x2 GEMM (xpre / yout) ----------------
__device__ __forceinline__ void gemm_tile(const float* __restrict__ A, int lda,
                                          const float* __restrict__ W, int ldw,
                                          float* __restrict__ C, int cld,
                                          const float* __restrict__ bias, int nch,
                                          u64* __restrict__ Sm) {
    const int tid = threadIdx.x, tx = tid & 15, ty = tid >> 4;
    u64 acc[8][8];
#pragma unroll
    for (int i = 0; i < 8; i++)
#pragma unroll
        for (int j = 0; j < 8; j++) acc[i][j] = 0ull;
    u64 rA[8], rB[16];
#pragma unroll
    for (int it = 0; it < 8; it++) {
        int idx = tid + 128 * it, row = idx >> 4, k8 = idx & 15;
        rA[it] = *reinterpret_cast<const u64*>(A + (size_t)row * lda + (k8 << 1));
    }
#pragma unroll
    for (int it = 0; it < 16; it++) {
        int idx = tid + 128 * it, row = idx >> 4, k8 = idx & 15;
        rB[it] = *reinterpret_cast<const u64*>(W + (size_t)row * ldw + (k8 << 1));
    }
    for (int c = 0; c < nch; c++) {
        u64* Ab = Sm + (c & 1) * 3072;
        u64* Bb = Ab + 1024;
#pragma unroll
        for (int it = 0; it < 8; it++) {
            int idx = tid + 128 * it, row = idx >> 4, k8 = idx & 15;
            Ab[(row << 4) + (k8 ^ ((row >> 3) & 15))] = rA[it];
        }
#pragma unroll
        for (int it = 0; it < 16; it++) {
            int idx = tid + 128 * it, row = idx >> 4, k8 = idx & 15;
            Bb[(row << 4) + (k8 ^ ((row >> 3) & 15))] = rB[it];
        }
        __syncthreads();
        if (c + 1 < nch) {
            const float* A2 = A + (c + 1) * 32;
            const float* W2 = W + (c + 1) * 32;
#pragma unroll
            for (int it = 0; it < 8; it++) {
                int idx = tid + 128 * it, row = idx >> 4, k8 = idx & 15;
                rA[it] = *reinterpret_cast<const u64*>(A2 + (size_t)row * lda + (k8 << 1));
            }
#pragma unroll
            for (int it = 0; it < 16; it++) {
                int idx = tid + 128 * it, row = idx >> 4, k8 = idx & 15;
                rB[it] = *reinterpret_cast<const u64*>(W2 + (size_t)row * ldw + (k8 << 1));
            }
        }
#pragma unroll
        for (int k8 = 0; k8 < 16; k8++) {
            u64 a2[8], b2[8];
#pragma unroll
            for (int i = 0; i < 8; i++) a2[i] = Ab[((ty * 8 + i) << 4) + (k8 ^ ty)];
#pragma unroll
            for (int j = 0; j < 8; j++) b2[j] = Bb[((tx * 8 + j) << 4) + (k8 ^ tx)];
#pragma unroll
            for (int i = 0; i < 8; i++)
#pragma unroll
                for (int j = 0; j < 8; j++) acc[i][j] = ffma2(a2[i], b2[j], acc[i][j]);
        }
    }
#pragma unroll
    for (int i = 0; i < 8; i++)
#pragma unroll
        for (int j = 0; j < 8; j++) {
            float v = psum(acc[i][j]);
            if (bias) v += bias[tx * 8 + j];
            C[(size_t)(ty * 8 + i) * cld + tx * 8 + j] = v;
        }
    __syncthreads();
}

// ---------------- kernels ----------------
__global__ void k_pad() {}

__global__ void k_conv(const float* __restrict__ Wh0, const float* __restrict__ Whr,
                       const float* __restrict__ Wxr) {
    const size_t NWH = (size_t)3 * 3072 * 1024;
    const size_t NTOT = (size_t)5 * 3072 * 1024;
    for (size_t i = (size_t)blockIdx.x * blockDim.x + threadIdx.x; i < NTOT;
         i += (size_t)gridDim.x * blockDim.x) {
        float w;
        bf16 *H, *L;
        size_t o;
        if (i < NWH) {
            o = i;
            w = (i < (size_t)3072 * 1024) ? Wh0[i] : Whr[i - (size_t)3072 * 1024];
            H = g_WhH; L = g_WhL;
        } else {
            o = i - NWH;
            w = Wxr[o];
            H = g_WxH; L = g_WxL;
        }
        bf16 h = __float2bfloat16_rn(w);
        H[o] = h;
        L[o] = __float2bfloat16_rn(w - __bfloat162float(h));
    }
}

__global__ __launch_bounds__(128, 2) void k_xpre(const float* __restrict__ x,
                                                 const float* __restrict__ Wx0) {
    __shared__ __align__(16) u64 Sm[6144];
    int n0 = blockIdx.x * 128, s = blockIdx.y;
    gemm_tile(x + (size_t)s * 128, 512 * 128, Wx0 + (size_t)n0 * 128, 128,
              g_Xpre + (size_t)s * 64 * 3072 + n0, 3072, nullptr, 4, Sm);
}

// persistent wavefront GRU: balanced 8-chunk jobs, hoisted decode, 4 barriers/wave
__global__ __launch_bounds__(NTHR) void k_gru(const float* __restrict__ bh0,
                                              const float* __restrict__ bhr) {
    extern __shared__ __align__(16) char dsm[];
    const u32 sm0 = smem_u32(dsm);
    const int tid = threadIdx.x, wid = tid >> 5, lane = tid & 31;
    const int mw = wid >> 1, nw = wid & 1;
    const int cta = blockIdx.x;
    const int gtid = cta * NTHR + tid;
    const int rlo = lane >> 2, cb = (lane & 3) * 2;
    const ptrdiff_t dWh = g_WhL - g_WhH;
    const ptrdiff_t dWx = g_WxL - g_WxH;

    for (int i = gtid; i < 2 * 3 * 65536; i += NCTA * NTHR) {
        (&g_hbuf[0][0][0])[i] = 0.f;
        (&g_hbH[0][0][0])[i] = __float2bfloat16_rn(0.f);
        (&g_hbL[0][0][0])[i] = __float2bfloat16_rn(0.f);
    }
    gridbar();

    for (int w = 0; w < 514; ++w) {
        const int rd = w & 1, wb = rd ^ 1;

        // ---- build Phase A jobs (once per wave) ----
        Job ja[3];
        int nv = 0;
#pragma unroll
        for (int k = 0; k < 3; k++) {
            int j = cta + k * NCTA;
            if (j >= 384) break;
            int l, tt, nh, kq;
            const bf16* AH;
            float* dst;
            if (j < 192) {  // zr h-path
                l = j >> 6;
                int r = j & 63;
                tt = r >> 2; nh = (r >> 1) & 1; kq = r & 1;
                AH = g_WhH + ((size_t)l * 3072 + tt * 128) * 1024 + kq * 512;
                dst = &g_pA[kq][l][tt * 128 * 64 + nh * 32];
                int t = w - l;
                if (t < 0 || t >= 512) continue;
                ja[nv].AH = AH; ja[nv].AL = AH + dWh;
                ja[nv].BH = g_hbH[rd][l] + nh * 32 * 1024 + kq * 512;
                ja[nv].BL = g_hbL[rd][l] + nh * 32 * 1024 + kq * 512;
                ja[nv].dst = dst;
                nv++;
            } else if (j < 320) {  // zr x-path
                int j2 = j - 192;
                int lm = j2 >> 6;
                int r = j2 & 63;
                tt = r >> 2; nh = (r >> 1) & 1; kq = r & 1;
                l = lm + 1;
                int t = w - l;
                if (t < 0 || t >= 512) continue;
                AH = g_WxH + ((size_t)lm * 3072 + tt * 128) * 1024 + kq * 512;
                ja[nv].AH = AH; ja[nv].AL = AH + dWx;
                ja[nv].BH = g_hbH[rd][lm] + nh * 32 * 1024 + kq * 512;
                ja[nv].BL = g_hbL[rd][lm] + nh * 32 * 1024 + kq * 512;
                ja[nv].dst = &g_pA[2 + kq][l][tt * 128 * 64 + nh * 32];
                nv++;
            } else {  // g x-path
                int j3 = j - 320;
                int lm = j3 >> 5;
                int r = j3 & 31;
                int tt8 = r >> 2; nh = (r >> 1) & 1; kq = r & 1;
                l = lm + 1;
                int t = w - l;
                if (t < 0 || t >= 512) continue;
                AH = g_WxH + ((size_t)lm * 3072 + 2048 + tt8 * 128) * 1024 + kq * 512;
                ja[nv].AH = AH; ja[nv].AL = AH + dWx;
                ja[nv].BH = g_hbH[rd][lm] + nh * 32 * 1024 + kq * 512;
                ja[nv].BL = g_hbL[rd][lm] + nh * 32 * 1024 + kq * 512;
                ja[nv].dst = &g_pC[kq][l][tt8 * 128 * 64 + nh * 32];
                nv++;
            }
        }
        run_jobs(ja, nv, sm0, tid, mw, nw, lane, rlo, cb);
        gridbar();

        // ---- EpiB: rh only (float4 over batch) ----
        for (int idx = gtid; idx < 3 * 1024 * 16; idx += NCTA * NTHR) {
            int l = idx / (1024 * 16);
            int rem = idx - l * (1024 * 16);
            int t = w - l;
            if (t < 0 || t >= 512) continue;
            int nn = rem >> 4;
            int b4 = (rem & 15) << 2;
            int n = 1024 + nn;
            int e0 = n * 64 + b4;
            float4 p0 = *reinterpret_cast<const float4*>(&g_pA[0][l][e0]);
            float4 p1 = *reinterpret_cast<const float4*>(&g_pA[1][l][e0]);
            float bv = (l == 0) ? bh0[n] : bhr[(l - 1) * 3072 + n];
            float v[4] = {p0.x + p1.x + bv, p0.y + p1.y + bv, p0.z + p1.z + bv,
                          p0.w + p1.w + bv};
            if (l > 0) {
                float4 p2 = *reinterpret_cast<const float4*>(&g_pA[2][l][e0]);
                float4 p3 = *reinterpret_cast<const float4*>(&g_pA[3][l][e0]);
                v[0] += p2.x + p3.x; v[1] += p2.y + p3.y;
                v[2] += p2.z + p3.z; v[3] += p2.w + p3.w;
            } else {
                const float* xp = &g_Xpre[((size_t)t * 64 + b4) * 3072 + n];
#pragma unroll
                for (int c = 0; c < 4; c++) v[c] += xp[(size_t)c * 3072];
            }
#pragma unroll
            for (int c = 0; c < 4; c++) {
                int b = b4 + c;
                float rv = sigm(v[c]) * g_hbuf[rd][l][b * 1024 + nn];
                bf16 hi = __float2bfloat16_rn(rv);
                g_rhH[l][b * 1024 + nn] = hi;
                g_rhL[l][b * 1024 + nn] = __float2bfloat16_rn(rv - __bfloat162float(hi));
            }
        }
        gridbar();

        // ---- Phase C: g rh-path (96 jobs, 1 per CTA) ----
        nv = 0;
        if (cta < 96) {
            int l = cta >> 5;
            int r = cta & 31;
            int tt8 = r >> 2, nh = (r >> 1) & 1, kq = r & 1;
            int t = w - l;
            if (t >= 0 && t < 512) {
                const bf16* AH =
                    g_WhH + ((size_t)l * 3072 + 2048 + tt8 * 128) * 1024 + kq * 512;
                ja[0].AH = AH; ja[0].AL = AH + dWh;
                ja[0].BH = g_rhH[l] + nh * 32 * 1024 + kq * 512;
                ja[0].BL = g_rhL[l] + nh * 32 * 1024 + kq * 512;
                ja[0].dst = &g_pC[2 + kq][l][tt8 * 128 * 64 + nh * 32];
                nv = 1;
            }
        }
        run_jobs(ja, nv, sm0, tid, mw, nw, lane, rlo, cb);
        gridbar();

        // ---- EpiD: z + g + h update (float4 over batch) ----
        for (int idx = gtid; idx < 3 * 1024 * 16; idx += NCTA * NTHR) {
            int l = idx / (1024 * 16);
            int rem = idx - l * (1024 * 16);
            int t = w - l;
            if (t < 0 || t >= 512) continue;
            int n = rem >> 4;
            int b4 = (rem & 15) << 2;
            int e0 = n * 64 + b4;
            const float* bias = (l == 0) ? bh0 : bhr + (l - 1) * 3072;
            float bz = bias[n], bg = bias[2048 + n];
            float4 a0 = *reinterpret_cast<const float4*>(&g_pA[0][l][e0]);
            float4 a1 = *reinterpret_cast<const float4*>(&g_pA[1][l][e0]);
            float4 c2 = *reinterpret_cast<const float4*>(&g_pC[2][l][e0]);
            float4 c3 = *reinterpret_cast<const float4*>(&g_pC[3][l][e0]);
            float vz[4] = {a0.x + a1.x + bz, a0.y + a1.y + bz, a0.z + a1.z + bz,
                           a0.w + a1.w + bz};
            float vg[4] = {c2.x + c3.x + bg, c2.y + c3.y + bg, c2.z + c3.z + bg,
                           c2.w + c3.w + bg};
            if (l > 0) {
                float4 a2 = *reinterpret_cast<const float4*>(&g_pA[2][l][e0]);
                float4 a3 = *reinterpret_cast<const float4*>(&g_pA[3][l][e0]);
                float4 c0 = *reinterpret_cast<const float4*>(&g_pC[0][l][e0]);
                float4 c1 = *reinterpret_cast<const float4*>(&g_pC[1][l][e0]);
                vz[0] += a2.x + a3.x; vz[1] += a2.y + a3.y;
                vz[2] += a2.z + a3.z; vz[3] += a2.w + a3.w;
                vg[0] += c0.x + c1.x; vg[1] += c0.y + c1.y;
                vg[2] += c0.z + c1.z; vg[3] += c0.w + c1.w;
            } else {
                const float* xp = &g_Xpre[((size_t)t * 64 + b4) * 3072];
#pragma unroll
                for (int c = 0; c < 4; c++) {
                    vz[c] += xp[(size_t)c * 3072 + n];
                    vg[c] += xp[(size_t)c * 3072 + 2048 + n];
                }
            }
#pragma unroll
            for (int c = 0; c < 4; c++) {
                int b = b4 + c;
                float z = sigm(vz[c]);
                float gg = tanhf(vg[c]);
                float hp = g_hbuf[rd][l][b * 1024 + n];
                float hn = z * hp + (1.f - z) * gg;
                g_hbuf[wb][l][b * 1024 + n] = hn;
                bf16 hi = __float2bfloat16_rn(hn);
                g_hbH[wb][l][b * 1024 + n] = hi;
                g_hbL[wb][l][b * 1024 + n] = __float2bfloat16_rn(hn - __bfloat162float(hi));
                if (l == 2) g_H2[((size_t)t * 64 + b) * 1024 + n] = hn;
            }
        }
        gridbar();
    }
}

__global__ __launch_bounds__(128, 2) void k_yout(const float* __restrict__ Wout,
                                                 const float* __restrict__ bout,
                                                 float* __restrict__ out) {
    __shared__ __align__(16) u64 Sm[6144];
    int s = blockIdx.x;
    gemm_tile(g_H2 + (size_t)s * 64 * 1024, 1024, Wout, 1024,
              out + (size_t)s * 128, 512 * 128, bout, 32, Sm);
}

__global__ void k_hout(float* __restrict__ out) {
    int i = blockIdx.x * 256 + threadIdx.x;
    if (i >= 3 * 64 * 1024) return;
    int l = i / (64 * 1024);
    int r = i % (64 * 1024);
    int b = r / 1024, n = r % 1024;
    out[(size_t)64 * 512 * 128 + ((size_t)b * 3 + l) * 1024 + n] = g_hbuf[l & 1][l][r];
}

extern "C" void kernel_launch(void* const* d_in, const int* in_sizes, int n_in,
                              void* d_out, int out_size) {
    const float* x = (const float*)d_in[0];
    const float* Wx0 = (const float*)d_in[1];
    const float* Wh0 = (const float*)d_in[2];
    const float* bh0 = (const float*)d_in[3];
    const float* Wxr = (const float*)d_in[4];
    const float* Whr = (const float*)d_in[5];
    const float* bhr = (const float*)d_in[6];
    const float* Wout = (const float*)d_in[7];
    const float* bout = (const float*)d_in[8];
    float* out = (float*)d_out;

    cudaFuncSetAttribute(k_gru, cudaFuncAttributeMaxDynamicSharedMemorySize, NSTAGE * BUFSZ);

    k_pad<<<1, 32>>>();
    k_conv<<<2048, 256>>>(Wh0, Whr, Wxr);
    k_xpre<<<dim3(24, 512), 128>>>(x, Wx0);
    k_gru<<<NCTA, NTHR, NSTAGE * BUFSZ>>>(bh0, bhr);  // my 4th launch -> ncu -s 5
    k_yout<<<512, 128>>>(Wout, bout, out);
    k_hout<<<(3 * 64 * 1024 + 255) / 256, 256>>>(out);
}

// round 13
// speedup vs baseline: 1.5098x; 1.2141x over previous
#include <cuda_runtime.h>
#include <cuda_fp16.h>
#include <cstddef>
#include <cstdint>

typedef unsigned long long u64;
typedef unsigned int u32;

#define NCTA 148
#define NTHR 512
#define NSTAGE 8

// smem chunk (bytes): A(fp16 W) 128x64 rows padded 144B; B actH/actL 32x64 each
#define OFF_BH 18432
#define OFF_BL 23040
#define BUFSZ 27648

// ---------------- device scratch ----------------
__device__ float g_Xpre[(size_t)512 * 64 * 3072];  // [t][b][3072]
__device__ float g_H2[(size_t)512 * 64 * 1024];    // [t][b][1024]
__device__ float g_hbuf[2][3][65536];              // fp32 h (parity, layer) [b][n]
__device__ __align__(16) __half g_hbH[2][3][65536];
__device__ __align__(16) __half g_hbL[2][3][65536];
__device__ __align__(16) __half g_rhH[3][65536];
__device__ __align__(16) __half g_rhL[3][65536];
__device__ __align__(16) __half g_WhF[(size_t)3 * 3072 * 1024];  // l0=Wh0, l1/2=Whr
__device__ __align__(16) __half g_WxF[(size_t)2 * 3072 * 1024];  // Wxr
// K-half partials, element layout [n*64 + b]
__device__ float g_pA[4][3][2048 * 64];  // zr: 0-1 h-path kq, 2-3 x-path kq
__device__ float g_pC[4][3][1024 * 64];  // g:  0-1 x-path kq, 2-3 rh-path kq
__device__ unsigned g_cnt;
__device__ volatile unsigned g_gen;

// ---------------- generic helpers ----------------
__device__ __forceinline__ u64 ffma2(u64 a, u64 b, u64 c) {
    u64 d;
    asm("fma.rn.f32x2 %0, %1, %2, %3;" : "=l"(d) : "l"(a), "l"(b), "l"(c));
    return d;
}
__device__ __forceinline__ float psum(u64 a) {
    float2 f = *reinterpret_cast<float2*>(&a);
    return f.x + f.y;
}
__device__ __forceinline__ float sigm(float x) { return 1.f / (1.f + __expf(-x)); }

__device__ __forceinline__ void gridbar() {
    __syncthreads();
    if (threadIdx.x == 0) {
        unsigned old = g_gen;
        __threadfence();
        if (atomicAdd(&g_cnt, 1u) == NCTA - 1) {
            g_cnt = 0;
            __threadfence();
            g_gen = old + 1;
        } else {
            while (g_gen == old) __nanosleep(32);
            __threadfence();
        }
    }
    __syncthreads();
}

// ---------------- mma / ldmatrix / cp.async primitives ----------------
__device__ __forceinline__ u32 smem_u32(const void* p) {
    u32 a;
    asm("{ .reg .u64 t; cvta.to.shared.u64 t, %1; cvt.u32.u64 %0, t; }" : "=r"(a) : "l"(p));
    return a;
}
__device__ __forceinline__ void mma16816(float* d, const u32* a, const u32* b) {
    asm volatile(
        "mma.sync.aligned.m16n8k16.row.col.f32.f16.f16.f32 "
        "{%0,%1,%2,%3}, {%4,%5,%6,%7}, {%8,%9}, {%0,%1,%2,%3};"
        : "+f"(d[0]), "+f"(d[1]), "+f"(d[2]), "+f"(d[3])
        : "r"(a[0]), "r"(a[1]), "r"(a[2]), "r"(a[3]), "r"(b[0]), "r"(b[1]));
}
__device__ __forceinline__ void ldm4(u32& r0, u32& r1, u32& r2, u32& r3, u32 addr) {
    asm volatile("ldmatrix.sync.aligned.m8n8.x4.shared.b16 {%0,%1,%2,%3}, [%4];"
                 : "=r"(r0), "=r"(r1), "=r"(r2), "=r"(r3) : "r"(addr));
}
__device__ __forceinline__ void cpa(u32 dst, const void* src) {
    asm volatile("cp.async.cg.shared.global [%0], [%1], 16;" :: "r"(dst), "l"(src) : "memory");
}
__device__ __forceinline__ void cp_commit() { asm volatile("cp.async.commit_group;" ::: "memory"); }
__device__ __forceinline__ void cp_waitN(int rem) {
    if (rem >= 5) asm volatile("cp.async.wait_group 5;" ::: "memory");
    else if (rem == 4) asm volatile("cp.async.wait_group 4;" ::: "memory");
    else if (rem == 3) asm volatile("cp.async.wait_group 3;" ::: "memory");
    else if (rem == 2) asm volatile("cp.async.wait_group 2;" ::: "memory");
    else if (rem == 1) asm volatile("cp.async.wait_group 1;" ::: "memory");
    else asm volatile("cp.async.wait_group 0;" ::: "memory");
}

struct Job { const __half *A, *BH, *BL; float* dst; };

__device__ __forceinline__ Job jsel(const Job ja[3], int k) {
    Job r = ja[0];
    if (k == 1) r = ja[1];
    if (k == 2) r = ja[2];
    return r;
}

// issue one K=64 chunk (W 128x64 fp16, actH/actL 32x64 fp16) into smem buffer
__device__ __forceinline__ void issue_chunk(u32 sbuf, const Job& s, int koff, int tid) {
#pragma unroll
    for (int it = 0; it < 2; it++) {
        int idx = tid + NTHR * it;
        int row = idx >> 3, c16 = idx & 7;
        u32 d = sbuf + row * 144 + c16 * 16;
        size_t so = (size_t)row * 1024 + koff + c16 * 8;
        cpa(d, s.A + so);
    }
    if (tid < 256) {
        int row = tid >> 3, c16 = tid & 7;
        u32 d = sbuf + OFF_BH + row * 144 + c16 * 16;
        size_t so = (size_t)row * 1024 + koff + c16 * 8;
        cpa(d, s.BH + so);
        cpa(d + (OFF_BL - OFF_BH), s.BL + so);
    }
    cp_commit();
}

// compute one K=64 chunk: 16 warps = 8(M) x 2(N); warp tile m16 x n16; 2 combos
__device__ __forceinline__ void mma_chunk(u32 sbuf, float (&acc)[2][4], int mw, int nw,
                                          int lane) {
    const int arow = ((lane >> 3) & 1) * 8 + (lane & 7);
    const int akk = ((lane >> 4) & 1) * 8;
    const int brow = ((lane >> 4) & 1) * 8 + (lane & 7);
    const int bkk = ((lane >> 3) & 1) * 8;
#pragma unroll
    for (int ks = 0; ks < 4; ks++) {
        int kOff = ks * 16;
        u32 aH[4];
        {
            int row = mw * 16 + arow;
            u32 ad = sbuf + row * 144 + (kOff + akk) * 2;
            ldm4(aH[0], aH[1], aH[2], aH[3], ad);
        }
        u32 bH[2][2], bL[2][2];
        {
            int nrow = nw * 16 + brow;
            u32 bd = sbuf + OFF_BH + nrow * 144 + (kOff + bkk) * 2;
            u32 r0, r1, r2, r3;
            ldm4(r0, r1, r2, r3, bd);
            bH[0][0] = r0; bH[0][1] = r1; bH[1][0] = r2; bH[1][1] = r3;
            ldm4(r0, r1, r2, r3, bd + (OFF_BL - OFF_BH));
            bL[0][0] = r0; bL[0][1] = r1; bL[1][0] = r2; bL[1][1] = r3;
        }
#pragma unroll
        for (int nt = 0; nt < 2; nt++) {
            mma16816(acc[nt], aH, bH[nt]);
            mma16816(acc[nt], aH, bL[nt]);
        }
    }
}

__device__ __forceinline__ void zero_acc(float (&acc)[2][4]) {
#pragma unroll
    for (int j = 0; j < 2; j++)
#pragma unroll
        for (int e = 0; e < 4; e++) acc[j][e] = 0.f;
}

// run nv jobs x 8 chunks, 8-stage ring, depth-6 prefetch, store fp32 partials
__device__ __forceinline__ void run_jobs(const Job ja[3], int nv, u32 sm0, int tid, int mw,
                                         int nw, int lane, int rlo, int cb) {
    if (nv == 0) return;
    float acc[2][4];
    zero_acc(acc);
    const int n = nv * 8;
#pragma unroll
    for (int j = 0; j < 6; j++)
        if (j < n) issue_chunk(sm0 + j * BUFSZ, jsel(ja, j >> 3), (j & 7) * 64, tid);
    for (int i = 0; i < n; i++) {
        int rem = n - 1 - i;
        cp_waitN(rem < 5 ? rem : 5);
        __syncthreads();
        int nx = i + 6;
        if (nx < n)
            issue_chunk(sm0 + (nx % NSTAGE) * BUFSZ, jsel(ja, nx >> 3), (nx & 7) * 64, tid);
        mma_chunk(sm0 + (i % NSTAGE) * BUFSZ, acc, mw, nw, lane);
        if ((i & 7) == 7) {
            float* dst = jsel(ja, i >> 3).dst;
#pragma unroll
            for (int half = 0; half < 2; half++) {
                int mrow = mw * 16 + half * 8 + rlo;
#pragma unroll
                for (int nt = 0; nt < 2; nt++)
#pragma unroll
                    for (int e = 0; e < 2; e++)
                        dst[mrow * 64 + nw * 16 + nt * 8 + cb + e] = acc[nt][half * 2 + e];
            }
            zero_acc(acc);
        }
    }
    __syncthreads();
}

// ---------------- SIMT f32x2 GEMM (xpre / yout) ----------------
__device__ __forceinline__ void gemm_tile(const float* __restrict__ A, int lda,
                                          const float* __restrict__ W, int ldw,
                                          float* __restrict__ C, int cld,
                                          const float* __restrict__ bias, int nch,
                                          u64* __restrict__ Sm) {
    const int tid = threadIdx.x, tx = tid & 15, ty = tid >> 4;
    u64 acc[8][8];
#pragma unroll
    for (int i = 0; i < 8; i++)
#pragma unroll
        for (int j = 0; j < 8; j++) acc[i][j] = 0ull;
    u64 rA[8], rB[16];
#pragma unroll
    for (int it = 0; it < 8; it++) {
        int idx = tid + 128 * it, row = idx >> 4, k8 = idx & 15;
        rA[it] = *reinterpret_cast<const u64*>(A + (size_t)row * lda + (k8 << 1));
    }
#pragma unroll
    for (int it = 0; it < 16; it++) {
        int idx = tid + 128 * it, row = idx >> 4, k8 = idx & 15;
        rB[it] = *reinterpret_cast<const u64*>(W + (size_t)row * ldw + (k8 << 1));
    }
    for (int c = 0; c < nch; c++) {
        u64* Ab = Sm + (c & 1) * 3072;
        u64* Bb = Ab + 1024;
#pragma unroll
        for (int it = 0; it < 8; it++) {
            int idx = tid + 128 * it, row = idx >> 4, k8 = idx & 15;
            Ab[(row << 4) + (k8 ^ ((row >> 3) & 15))] = rA[it];
        }
#pragma unroll
        for (int it = 0; it < 16; it++) {
            int idx = tid + 128 * it, row = idx >> 4, k8 = idx & 15;
            Bb[(row << 4) + (k8 ^ ((row >> 3) & 15))] = rB[it];
        }
        __syncthreads();
        if (c + 1 < nch) {
            const float* A2 = A + (c + 1) * 32;
            const float* W2 = W + (c + 1) * 32;
#pragma unroll
            for (int it = 0; it < 8; it++) {
                int idx = tid + 128 * it, row = idx >> 4, k8 = idx & 15;
                rA[it] = *reinterpret_cast<const u64*>(A2 + (size_t)row * lda + (k8 << 1));
            }
#pragma unroll
            for (int it = 0; it < 16; it++) {
                int idx = tid + 128 * it, row = idx >> 4, k8 = idx & 15;
                rB[it] = *reinterpret_cast<const u64*>(W2 + (size_t)row * ldw + (k8 << 1));
            }
        }
#pragma unroll
        for (int k8 = 0; k8 < 16; k8++) {
            u64 a2[8], b2[8];
#pragma unroll
            for (int i = 0; i < 8; i++) a2[i] = Ab[((ty * 8 + i) << 4) + (k8 ^ ty)];
#pragma unroll
            for (int j = 0; j < 8; j++) b2[j] = Bb[((tx * 8 + j) << 4) + (k8 ^ tx)];
#pragma unroll
            for (int i = 0; i < 8; i++)
#pragma unroll
                for (int j = 0; j < 8; j++) acc[i][j] = ffma2(a2[i], b2[j], acc[i][j]);
        }
    }
#pragma unroll
    for (int i = 0; i < 8; i++)
#pragma unroll
        for (int j = 0; j < 8; j++) {
            float v = psum(acc[i][j]);
            if (bias) v += bias[tx * 8 + j];
            C[(size_t)(ty * 8 + i) * cld + tx * 8 + j] = v;
        }
    __syncthreads();
}

// ---------------- kernels ----------------
__global__ void k_pad() {}

// weights fp32 -> fp16
__global__ void k_conv(const float* __restrict__ Wh0, const float* __restrict__ Whr,
                       const float* __restrict__ Wxr) {
    const size_t NWH = (size_t)3 * 3072 * 1024;
    const size_t NTOT = (size_t)5 * 3072 * 1024;
    for (size_t i = (size_t)blockIdx.x * blockDim.x + threadIdx.x; i < NTOT;
         i += (size_t)gridDim.x * blockDim.x) {
        if (i < NWH) {
            float w = (i < (size_t)3072 * 1024) ? Wh0[i] : Whr[i - (size_t)3072 * 1024];
            g_WhF[i] = __float2half_rn(w);
        } else {
            size_t o = i - NWH;
            g_WxF[o] = __float2half_rn(Wxr[o]);
        }
    }
}

__global__ __launch_bounds__(128, 2) void k_xpre(const float* __restrict__ x,
                                                 const float* __restrict__ Wx0) {
    __shared__ __align__(16) u64 Sm[6144];
    int n0 = blockIdx.x * 128, s = blockIdx.y;
    gemm_tile(x + (size_t)s * 128, 512 * 128, Wx0 + (size_t)n0 * 128, 128,
              g_Xpre + (size_t)s * 64 * 3072 + n0, 3072, nullptr, 4, Sm);
}

// persistent wavefront GRU: fp16 weights + fp16 hi/lo acts, 2 combos, 4 barriers/wave
__global__ __launch_bounds__(NTHR) void k_gru(const float* __restrict__ bh0,
                                              const float* __restrict__ bhr) {
    extern __shared__ __align__(16) char dsm[];
    const u32 sm0 = smem_u32(dsm);
    const int tid = threadIdx.x, wid = tid >> 5, lane = tid & 31;
    const int mw = wid >> 1, nw = wid & 1;
    const int cta = blockIdx.x;
    const int gtid = cta * NTHR + tid;
    const int rlo = lane >> 2, cb = (lane & 3) * 2;

    for (int i = gtid; i < 2 * 3 * 65536; i += NCTA * NTHR) {
        (&g_hbuf[0][0][0])[i] = 0.f;
        (&g_hbH[0][0][0])[i] = __float2half_rn(0.f);
        (&g_hbL[0][0][0])[i] = __float2half_rn(0.f);
    }
    gridbar();

    for (int w = 0; w < 514; ++w) {
        const int rd = w & 1, wb = rd ^ 1;

        // ---- build Phase A jobs (once per wave) ----
        Job ja[3];
        int nv = 0;
#pragma unroll
        for (int k = 0; k < 3; k++) {
            int j = cta + k * NCTA;
            if (j >= 384) break;
            if (j < 192) {  // zr h-path
                int l = j >> 6;
                int r = j & 63;
                int tt = r >> 2, nh = (r >> 1) & 1, kq = r & 1;
                int t = w - l;
                if (t < 0 || t >= 512) continue;
                ja[nv].A = g_WhF + ((size_t)l * 3072 + tt * 128) * 1024 + kq * 512;
                ja[nv].BH = g_hbH[rd][l] + nh * 32 * 1024 + kq * 512;
                ja[nv].BL = g_hbL[rd][l] + nh * 32 * 1024 + kq * 512;
                ja[nv].dst = &g_pA[kq][l][tt * 128 * 64 + nh * 32];
                nv++;
            } else if (j < 320) {  // zr x-path
                int j2 = j - 192;
                int lm = j2 >> 6;
                int r = j2 & 63;
                int tt = r >> 2, nh = (r >> 1) & 1, kq = r & 1;
                int l = lm + 1;
                int t = w - l;
                if (t < 0 || t >= 512) continue;
                ja[nv].A = g_WxF + ((size_t)lm * 3072 + tt * 128) * 1024 + kq * 512;
                ja[nv].BH = g_hbH[rd][lm] + nh * 32 * 1024 + kq * 512;
                ja[nv].BL = g_hbL[rd][lm] + nh * 32 * 1024 + kq * 512;
                ja[nv].dst = &g_pA[2 + kq][l][tt * 128 * 64 + nh * 32];
                nv++;
            } else {  // g x-path
                int j3 = j - 320;
                int lm = j3 >> 5;
                int r = j3 & 31;
                int tt8 = r >> 2, nh = (r >> 1) & 1, kq = r & 1;
                int l = lm + 1;
                int t = w - l;
                if (t < 0 || t >= 512) continue;
                ja[nv].A = g_WxF + ((size_t)lm * 3072 + 2048 + tt8 * 128) * 1024 + kq * 512;
                ja[nv].BH = g_hbH[rd][lm] + nh * 32 * 1024 + kq * 512;
                ja[nv].BL = g_hbL[rd][lm] + nh * 32 * 1024 + kq * 512;
                ja[nv].dst = &g_pC[kq][l][tt8 * 128 * 64 + nh * 32];
                nv++;
            }
        }
        run_jobs(ja, nv, sm0, tid, mw, nw, lane, rlo, cb);
        gridbar();

        // ---- EpiB: rh only (float4 over batch) ----
        for (int idx = gtid; idx < 3 * 1024 * 16; idx += NCTA * NTHR) {
            int l = idx / (1024 * 16);
            int rem = idx - l * (1024 * 16);
            int t = w - l;
            if (t < 0 || t >= 512) continue;
            int nn = rem >> 4;
            int b4 = (rem & 15) << 2;
            int n = 1024 + nn;
            int e0 = n * 64 + b4;
            float4 p0 = *reinterpret_cast<const float4*>(&g_pA[0][l][e0]);
            float4 p1 = *reinterpret_cast<const float4*>(&g_pA[1][l][e0]);
            float bv = (l == 0) ? bh0[n] : bhr[(l - 1) * 3072 + n];
            float v[4] = {p0.x + p1.x + bv, p0.y + p1.y + bv, p0.z + p1.z + bv,
                          p0.w + p1.w + bv};
            if (l > 0) {
                float4 p2 = *reinterpret_cast<const float4*>(&g_pA[2][l][e0]);
                float4 p3 = *reinterpret_cast<const float4*>(&g_pA[3][l][e0]);
                v[0] += p2.x + p3.x; v[1] += p2.y + p3.y;
                v[2] += p2.z + p3.z; v[3] += p2.w + p3.w;
            } else {
                const float* xp = &g_Xpre[((size_t)t * 64 + b4) * 3072 + n];
#pragma unroll
                for (int c = 0; c < 4; c++) v[c] += xp[(size_t)c * 3072];
            }
#pragma unroll
            for (int c = 0; c < 4; c++) {
                int b = b4 + c;
                float rv = sigm(v[c]) * g_hbuf[rd][l][b * 1024 + nn];
                __half hi = __float2half_rn(rv);
                g_rhH[l][b * 1024 + nn] = hi;
                g_rhL[l][b * 1024 + nn] = __float2half_rn(rv - __half2float(hi));
            }
        }
        gridbar();

        // ---- Phase C: g rh-path (96 jobs, 1 per CTA) ----
        nv = 0;
        if (cta < 96) {
            int l = cta >> 5;
            int r = cta & 31;
            int tt8 = r >> 2, nh = (r >> 1) & 1, kq = r & 1;
            int t = w - l;
            if (t >= 0 && t < 512) {
                ja[0].A = g_WhF + ((size_t)l * 3072 + 2048 + tt8 * 128) * 1024 + kq * 512;
                ja[0].BH = g_rhH[l] + nh * 32 * 1024 + kq * 512;
                ja[0].BL = g_rhL[l] + nh * 32 * 1024 + kq * 512;
                ja[0].dst = &g_pC[2 + kq][l][tt8 * 128 * 64 + nh * 32];
                nv = 1;
            }
        }
        run_jobs(ja, nv, sm0, tid, mw, nw, lane, rlo, cb);
        gridbar();

        // ---- EpiD: z + g + h update (float4 over batch) ----
        for (int idx = gtid; idx < 3 * 1024 * 16; idx += NCTA * NTHR) {
            int l = idx / (1024 * 16);
            int rem = idx - l * (1024 * 16);
            int t = w - l;
            if (t < 0 || t >= 512) continue;
            int n = rem >> 4;
            int b4 = (rem & 15) << 2;
            int e0 = n * 64 + b4;
            const float* bias = (l == 0) ? bh0 : bhr + (l - 1) * 3072;
            float bz = bias[n], bg = bias[2048 + n];
            float4 a0 = *reinterpret_cast<const float4*>(&g_pA[0][l][e0]);
            float4 a1 = *reinterpret_cast<const float4*>(&g_pA[1][l][e0]);
            float4 c2 = *reinterpret_cast<const float4*>(&g_pC[2][l][e0]);
            float4 c3 = *reinterpret_cast<const float4*>(&g_pC[3][l][e0]);
            float vz[4] = {a0.x + a1.x + bz, a0.y + a1.y + bz, a0.z + a1.z + bz,
                           a0.w + a1.w + bz};
            float vg[4] = {c2.x + c3.x + bg, c2.y + c3.y + bg, c2.z + c3.z + bg,
                           c2.w + c3.w + bg};
            if (l > 0) {
                float4 a2 = *reinterpret_cast<const float4*>(&g_pA[2][l][e0]);
                float4 a3 = *reinterpret_cast<const float4*>(&g_pA[3][l][e0]);
                float4 c0 = *reinterpret_cast<const float4*>(&g_pC[0][l][e0]);
                float4 c1 = *reinterpret_cast<const float4*>(&g_pC[1][l][e0]);
                vz[0] += a2.x + a3.x; vz[1] += a2.y + a3.y;
                vz[2] += a2.z + a3.z; vz[3] += a2.w + a3.w;
                vg[0] += c0.x + c1.x; vg[1] += c0.y + c1.y;
                vg[2] += c0.z + c1.z; vg[3] += c0.w + c1.w;
            } else {
                const float* xp = &g_Xpre[((size_t)t * 64 + b4) * 3072];
#pragma unroll
                for (int c = 0; c < 4; c++) {
                    vz[c] += xp[(size_t)c * 3072 + n];
                    vg[c] += xp[(size_t)c * 3072 + 2048 + n];
                }
            }
#pragma unroll
            for (int c = 0; c < 4; c++) {
                int b = b4 + c;
                float z = sigm(vz[c]);
                float gg = tanhf(vg[c]);
                float hp = g_hbuf[rd][l][b * 1024 + n];
                float hn = z * hp + (1.f - z) * gg;
                g_hbuf[wb][l][b * 1024 + n] = hn;
                __half hi = __float2half_rn(hn);
                g_hbH[wb][l][b * 1024 + n] = hi;
                g_hbL[wb][l][b * 1024 + n] = __float2half_rn(hn - __half2float(hi));
                if (l == 2) g_H2[((size_t)t * 64 + b) * 1024 + n] = hn;
            }
        }
        gridbar();
    }
}

__global__ __launch_bounds__(128, 2) void k_yout(const float* __restrict__ Wout,
                                                 const float* __restrict__ bout,
                                                 float* __restrict__ out) {
    __shared__ __align__(16) u64 Sm[6144];
    int s = blockIdx.x;
    gemm_tile(g_H2 + (size_t)s * 64 * 1024, 1024, Wout, 1024,
              out + (size_t)s * 128, 512 * 128, bout, 32, Sm);
}

__global__ void k_hout(float* __restrict__ out) {
    int i = blockIdx.x * 256 + threadIdx.x;
    if (i >= 3 * 64 * 1024) return;
    int l = i / (64 * 1024);
    int r = i % (64 * 1024);
    int b = r / 1024, n = r % 1024;
    out[(size_t)64 * 512 * 128 + ((size_t)b * 3 + l) * 1024 + n] = g_hbuf[l & 1][l][r];
}

extern "C" void kernel_launch(void* const* d_in, const int* in_sizes, int n_in,
                              void* d_out, int out_size) {
    const float* x = (const float*)d_in[0];
    const float* Wx0 = (const float*)d_in[1];
    const float* Wh0 = (const float*)d_in[2];
    const float* bh0 = (const float*)d_in[3];
    const float* Wxr = (const float*)d_in[4];
    const float* Whr = (const float*)d_in[5];
    const float* bhr = (const float*)d_in[6];
    const float* Wout = (const float*)d_in[7];
    const float* bout = (const float*)d_in[8];
    float* out = (float*)d_out;

    cudaFuncSetAttribute(k_gru, cudaFuncAttributeMaxDynamicSharedMemorySize, NSTAGE * BUFSZ);

    k_pad<<<1, 32>>>();
    k_conv<<<2048, 256>>>(Wh0, Whr, Wxr);
    k_xpre<<<dim3(24, 512), 128>>>(x, Wx0);
    k_gru<<<NCTA, NTHR, NSTAGE * BUFSZ>>>(bh0, bhr);  // my 4th launch -> ncu -s 5
    k_yout<<<512, 128>>>(Wout, bout, out);
    k_hout<<<(3 * 64 * 1024 + 255) / 256, 256>>>(out);
}

// round 14
// speedup vs baseline: 1.8179x; 1.2041x over previous
#include <cuda_runtime.h>
#include <cuda_fp16.h>
#include <cstddef>
#include <cstdint>

typedef unsigned long long u64;
typedef unsigned int u32;

#define NCTA 148
#define NTHR 512
#define NSTAGE 8

// smem chunk (bytes): A(fp16 W) 128x64 rows padded 144B; B act 32x64
#define OFF_BH 18432
#define BUFSZ 23040

// ---------------- device scratch ----------------
__device__ float g_Xpre[(size_t)512 * 64 * 3072];  // [t][b][3072]
__device__ float g_H2[(size_t)512 * 64 * 1024];    // [t][b][1024]
__device__ float g_hbuf[2][3][65536];              // fp32 h (parity, layer) [b][n]
__device__ __align__(16) __half g_hbH[2][3][65536];
__device__ __align__(16) __half g_rhH[3][65536];
__device__ __align__(16) __half g_WhF[(size_t)3 * 3072 * 1024];  // l0=Wh0, l1/2=Whr
__device__ __align__(16) __half g_WxF[(size_t)2 * 3072 * 1024];  // Wxr
// K-half partials, element layout [n*64 + b]
__device__ float g_pA[4][3][2048 * 64];  // zr: 0-1 h-path kq, 2-3 x-path kq
__device__ float g_pC[4][3][1024 * 64];  // g:  0-1 x-path kq, 2-3 rh-path kq
__device__ unsigned g_cnt;
__device__ volatile unsigned g_gen;

// ---------------- generic helpers ----------------
__device__ __forceinline__ u64 ffma2(u64 a, u64 b, u64 c) {
    u64 d;
    asm("fma.rn.f32x2 %0, %1, %2, %3;" : "=l"(d) : "l"(a), "l"(b), "l"(c));
    return d;
}
__device__ __forceinline__ float psum(u64 a) {
    float2 f = *reinterpret_cast<float2*>(&a);
    return f.x + f.y;
}
__device__ __forceinline__ float sigm(float x) { return 1.f / (1.f + __expf(-x)); }

__device__ __forceinline__ void gridbar() {
    __syncthreads();
    if (threadIdx.x == 0) {
        unsigned old = g_gen;
        __threadfence();
        if (atomicAdd(&g_cnt, 1u) == NCTA - 1) {
            g_cnt = 0;
            __threadfence();
            g_gen = old + 1;
        } else {
            while (g_gen == old) __nanosleep(32);
            __threadfence();
        }
    }
    __syncthreads();
}

// ---------------- mma / ldmatrix / cp.async primitives ----------------
__device__ __forceinline__ u32 smem_u32(const void* p) {
    u32 a;
    asm("{ .reg .u64 t; cvta.to.shared.u64 t, %1; cvt.u32.u64 %0, t; }" : "=r"(a) : "l"(p));
    return a;
}
__device__ __forceinline__ void mma16816(float* d, const u32* a, const u32* b) {
    asm volatile(
        "mma.sync.aligned.m16n8k16.row.col.f32.f16.f16.f32 "
        "{%0,%1,%2,%3}, {%4,%5,%6,%7}, {%8,%9}, {%0,%1,%2,%3};"
        : "+f"(d[0]), "+f"(d[1]), "+f"(d[2]), "+f"(d[3])
        : "r"(a[0]), "r"(a[1]), "r"(a[2]), "r"(a[3]), "r"(b[0]), "r"(b[1]));
}
__device__ __forceinline__ void ldm4(u32& r0, u32& r1, u32& r2, u32& r3, u32 addr) {
    asm volatile("ldmatrix.sync.aligned.m8n8.x4.shared.b16 {%0,%1,%2,%3}, [%4];"
                 : "=r"(r0), "=r"(r1), "=r"(r2), "=r"(r3) : "r"(addr));
}
__device__ __forceinline__ void cpa(u32 dst, const void* src) {
    asm volatile("cp.async.cg.shared.global [%0], [%1], 16;" :: "r"(dst), "l"(src) : "memory");
}
__device__ __forceinline__ void cp_commit() { asm volatile("cp.async.commit_group;" ::: "memory"); }
__device__ __forceinline__ void cp_waitN(int rem) {
    if (rem >= 5) asm volatile("cp.async.wait_group 5;" ::: "memory");
    else if (rem == 4) asm volatile("cp.async.wait_group 4;" ::: "memory");
    else if (rem == 3) asm volatile("cp.async.wait_group 3;" ::: "memory");
    else if (rem == 2) asm volatile("cp.async.wait_group 2;" ::: "memory");
    else if (rem == 1) asm volatile("cp.async.wait_group 1;" ::: "memory");
    else asm volatile("cp.async.wait_group 0;" ::: "memory");
}

struct Job { const __half *A, *BH; float* dst; };

__device__ __forceinline__ Job jsel(const Job ja[3], int k) {
    Job r = ja[0];
    if (k == 1) r = ja[1];
    if (k == 2) r = ja[2];
    return r;
}

// issue one K=64 chunk (W 128x64 fp16, act 32x64 fp16) into smem buffer
__device__ __forceinline__ void issue_chunk(u32 sbuf, const Job& s, int koff, int tid) {
#pragma unroll
    for (int it = 0; it < 2; it++) {
        int idx = tid + NTHR * it;
        int row = idx >> 3, c16 = idx & 7;
        u32 d = sbuf + row * 144 + c16 * 16;
        size_t so = (size_t)row * 1024 + koff + c16 * 8;
        cpa(d, s.A + so);
    }
    if (tid < 256) {
        int row = tid >> 3, c16 = tid & 7;
        u32 d = sbuf + OFF_BH + row * 144 + c16 * 16;
        size_t so = (size_t)row * 1024 + koff + c16 * 8;
        cpa(d, s.BH + so);
    }
    cp_commit();
}

// compute one K=64 chunk: 16 warps = 8(M) x 2(N); warp tile m16 x n16; 1 combo
__device__ __forceinline__ void mma_chunk(u32 sbuf, float (&acc)[2][4], int mw, int nw,
                                          int lane) {
    const int arow = ((lane >> 3) & 1) * 8 + (lane & 7);
    const int akk = ((lane >> 4) & 1) * 8;
    const int brow = ((lane >> 4) & 1) * 8 + (lane & 7);
    const int bkk = ((lane >> 3) & 1) * 8;
#pragma unroll
    for (int ks = 0; ks < 4; ks++) {
        int kOff = ks * 16;
        u32 aH[4];
        {
            int row = mw * 16 + arow;
            u32 ad = sbuf + row * 144 + (kOff + akk) * 2;
            ldm4(aH[0], aH[1], aH[2], aH[3], ad);
        }
        u32 bH[2][2];
        {
            int nrow = nw * 16 + brow;
            u32 bd = sbuf + OFF_BH + nrow * 144 + (kOff + bkk) * 2;
            u32 r0, r1, r2, r3;
            ldm4(r0, r1, r2, r3, bd);
            bH[0][0] = r0; bH[0][1] = r1; bH[1][0] = r2; bH[1][1] = r3;
        }
#pragma unroll
        for (int nt = 0; nt < 2; nt++) mma16816(acc[nt], aH, bH[nt]);
    }
}

__device__ __forceinline__ void zero_acc(float (&acc)[2][4]) {
#pragma unroll
    for (int j = 0; j < 2; j++)
#pragma unroll
        for (int e = 0; e < 4; e++) acc[j][e] = 0.f;
}

// run nv jobs x 8 chunks, 8-stage ring, depth-6 prefetch, store fp32 partials
__device__ __forceinline__ void run_jobs(const Job ja[3], int nv, u32 sm0, int tid, int mw,
                                         int nw, int lane, int rlo, int cb) {
    if (nv == 0) return;
    float acc[2][4];
    zero_acc(acc);
    const int n = nv * 8;
#pragma unroll
    for (int j = 0; j < 6; j++)
        if (j < n) issue_chunk(sm0 + j * BUFSZ, jsel(ja, j >> 3), (j & 7) * 64, tid);
    for (int i = 0; i < n; i++) {
        int rem = n - 1 - i;
        cp_waitN(rem < 5 ? rem : 5);
        __syncthreads();
        int nx = i + 6;
        if (nx < n)
            issue_chunk(sm0 + (nx % NSTAGE) * BUFSZ, jsel(ja, nx >> 3), (nx & 7) * 64, tid);
        mma_chunk(sm0 + (i % NSTAGE) * BUFSZ, acc, mw, nw, lane);
        if ((i & 7) == 7) {
            float* dst = jsel(ja, i >> 3).dst;
#pragma unroll
            for (int half = 0; half < 2; half++) {
                int mrow = mw * 16 + half * 8 + rlo;
#pragma unroll
                for (int nt = 0; nt < 2; nt++)
#pragma unroll
                    for (int e = 0; e < 2; e++)
                        dst[mrow * 64 + nw * 16 + nt * 8 + cb + e] = acc[nt][half * 2 + e];
            }
            zero_acc(acc);
        }
    }
    __syncthreads();
}

// ---------------- SIMT f32x2 GEMM (xpre / yout) ----------------
__device__ __forceinline__ void gemm_tile(const float* __restrict__ A, int lda,
                                          const float* __restrict__ W, int ldw,
                                          float* __restrict__ C, int cld,
                                          const float* __restrict__ bias, int nch,
                                          u64* __restrict__ Sm) {
    const int tid = threadIdx.x, tx = tid & 15, ty = tid >> 4;
    u64 acc[8][8];
#pragma unroll
    for (int i = 0; i < 8; i++)
#pragma unroll
        for (int j = 0; j < 8; j++) acc[i][j] = 0ull;
    u64 rA[8], rB[16];
#pragma unroll
    for (int it = 0; it < 8; it++) {
        int idx = tid + 128 * it, row = idx >> 4, k8 = idx & 15;
        rA[it] = *reinterpret_cast<const u64*>(A + (size_t)row * lda + (k8 << 1));
    }
#pragma unroll
    for (int it = 0; it < 16; it++) {
        int idx = tid + 128 * it, row = idx >> 4, k8 = idx & 15;
        rB[it] = *reinterpret_cast<const u64*>(W + (size_t)row * ldw + (k8 << 1));
    }
    for (int c = 0; c < nch; c++) {
        u64* Ab = Sm + (c & 1) * 3072;
        u64* Bb = Ab + 1024;
#pragma unroll
        for (int it = 0; it < 8; it++) {
            int idx = tid + 128 * it, row = idx >> 4, k8 = idx & 15;
            Ab[(row << 4) + (k8 ^ ((row >> 3) & 15))] = rA[it];
        }
#pragma unroll
        for (int it = 0; it < 16; it++) {
            int idx = tid + 128 * it, row = idx >> 4, k8 = idx & 15;
            Bb[(row << 4) + (k8 ^ ((row >> 3) & 15))] = rB[it];
        }
        __syncthreads();
        if (c + 1 < nch) {
            const float* A2 = A + (c + 1) * 32;
            const float* W2 = W + (c + 1) * 32;
#pragma unroll
            for (int it = 0; it < 8; it++) {
                int idx = tid + 128 * it, row = idx >> 4, k8 = idx & 15;
                rA[it] = *reinterpret_cast<const u64*>(A2 + (size_t)row * lda + (k8 << 1));
            }
#pragma unroll
            for (int it = 0; it < 16; it++) {
                int idx = tid + 128 * it, row = idx >> 4, k8 = idx & 15;
                rB[it] = *reinterpret_cast<const u64*>(W2 + (size_t)row * ldw + (k8 << 1));
            }
        }
#pragma unroll
        for (int k8 = 0; k8 < 16; k8++) {
            u64 a2[8], b2[8];
#pragma unroll
            for (int i = 0; i < 8; i++) a2[i] = Ab[((ty * 8 + i) << 4) + (k8 ^ ty)];
#pragma unroll
            for (int j = 0; j < 8; j++) b2[j] = Bb[((tx * 8 + j) << 4) + (k8 ^ tx)];
#pragma unroll
            for (int i = 0; i < 8; i++)
#pragma unroll
                for (int j = 0; j < 8; j++) acc[i][j] = ffma2(a2[i], b2[j], acc[i][j]);
        }
    }
#pragma unroll
    for (int i = 0; i < 8; i++)
#pragma unroll
        for (int j = 0; j < 8; j++) {
            float v = psum(acc[i][j]);
            if (bias) v += bias[tx * 8 + j];
            C[(size_t)(ty * 8 + i) * cld + tx * 8 + j] = v;
        }
    __syncthreads();
}

// ---------------- kernels ----------------
__global__ void k_pad() {}

// weights fp32 -> fp16
__global__ void k_conv(const float* __restrict__ Wh0, const float* __restrict__ Whr,
                       const float* __restrict__ Wxr) {
    const size_t NWH = (size_t)3 * 3072 * 1024;
    const size_t NTOT = (size_t)5 * 3072 * 1024;
    for (size_t i = (size_t)blockIdx.x * blockDim.x + threadIdx.x; i < NTOT;
         i += (size_t)gridDim.x * blockDim.x) {
        if (i < NWH) {
            float w = (i < (size_t)3072 * 1024) ? Wh0[i] : Whr[i - (size_t)3072 * 1024];
            g_WhF[i] = __float2half_rn(w);
        } else {
            size_t o = i - NWH;
            g_WxF[o] = __float2half_rn(Wxr[o]);
        }
    }
}

__global__ __launch_bounds__(128, 2) void k_xpre(const float* __restrict__ x,
                                                 const float* __restrict__ Wx0) {
    __shared__ __align__(16) u64 Sm[6144];
    int n0 = blockIdx.x * 128, s = blockIdx.y;
    gemm_tile(x + (size_t)s * 128, 512 * 128, Wx0 + (size_t)n0 * 128, 128,
              g_Xpre + (size_t)s * 64 * 3072 + n0, 3072, nullptr, 4, Sm);
}

// persistent wavefront GRU: fp16 weights + fp16 acts, 1 combo, 4 barriers/wave
__global__ __launch_bounds__(NTHR) void k_gru(const float* __restrict__ bh0,
                                              const float* __restrict__ bhr) {
    extern __shared__ __align__(16) char dsm[];
    const u32 sm0 = smem_u32(dsm);
    const int tid = threadIdx.x, wid = tid >> 5, lane = tid & 31;
    const int mw = wid >> 1, nw = wid & 1;
    const int cta = blockIdx.x;
    const int gtid = cta * NTHR + tid;
    const int rlo = lane >> 2, cb = (lane & 3) * 2;

    for (int i = gtid; i < 2 * 3 * 65536; i += NCTA * NTHR) {
        (&g_hbuf[0][0][0])[i] = 0.f;
        (&g_hbH[0][0][0])[i] = __float2half_rn(0.f);
    }
    gridbar();

    for (int w = 0; w < 514; ++w) {
        const int rd = w & 1, wb = rd ^ 1;

        // ---- build Phase A jobs (once per wave) ----
        Job ja[3];
        int nv = 0;
#pragma unroll
        for (int k = 0; k < 3; k++) {
            int j = cta + k * NCTA;
            if (j >= 384) break;
            if (j < 192) {  // zr h-path
                int l = j >> 6;
                int r = j & 63;
                int tt = r >> 2, nh = (r >> 1) & 1, kq = r & 1;
                int t = w - l;
                if (t < 0 || t >= 512) continue;
                ja[nv].A = g_WhF + ((size_t)l * 3072 + tt * 128) * 1024 + kq * 512;
                ja[nv].BH = g_hbH[rd][l] + nh * 32 * 1024 + kq * 512;
                ja[nv].dst = &g_pA[kq][l][tt * 128 * 64 + nh * 32];
                nv++;
            } else if (j < 320) {  // zr x-path
                int j2 = j - 192;
                int lm = j2 >> 6;
                int r = j2 & 63;
                int tt = r >> 2, nh = (r >> 1) & 1, kq = r & 1;
                int l = lm + 1;
                int t = w - l;
                if (t < 0 || t >= 512) continue;
                ja[nv].A = g_WxF + ((size_t)lm * 3072 + tt * 128) * 1024 + kq * 512;
                ja[nv].BH = g_hbH[rd][lm] + nh * 32 * 1024 + kq * 512;
                ja[nv].dst = &g_pA[2 + kq][l][tt * 128 * 64 + nh * 32];
                nv++;
            } else {  // g x-path
                int j3 = j - 320;
                int lm = j3 >> 5;
                int r = j3 & 31;
                int tt8 = r >> 2, nh = (r >> 1) & 1, kq = r & 1;
                int l = lm + 1;
                int t = w - l;
                if (t < 0 || t >= 512) continue;
                ja[nv].A = g_WxF + ((size_t)lm * 3072 + 2048 + tt8 * 128) * 1024 + kq * 512;
                ja[nv].BH = g_hbH[rd][lm] + nh * 32 * 1024 + kq * 512;
                ja[nv].dst = &g_pC[kq][l][tt8 * 128 * 64 + nh * 32];
                nv++;
            }
        }
        run_jobs(ja, nv, sm0, tid, mw, nw, lane, rlo, cb);
        gridbar();

        // ---- EpiB: rh only (float4 over batch) ----
        for (int idx = gtid; idx < 3 * 1024 * 16; idx += NCTA * NTHR) {
            int l = idx / (1024 * 16);
            int rem = idx - l * (1024 * 16);
            int t = w - l;
            if (t < 0 || t >= 512) continue;
            int nn = rem >> 4;
            int b4 = (rem & 15) << 2;
            int n = 1024 + nn;
            int e0 = n * 64 + b4;
            float4 p0 = *reinterpret_cast<const float4*>(&g_pA[0][l][e0]);
            float4 p1 = *reinterpret_cast<const float4*>(&g_pA[1][l][e0]);
            float bv = (l == 0) ? bh0[n] : bhr[(l - 1) * 3072 + n];
            float v[4] = {p0.x + p1.x + bv, p0.y + p1.y + bv, p0.z + p1.z + bv,
                          p0.w + p1.w + bv};
            if (l > 0) {
                float4 p2 = *reinterpret_cast<const float4*>(&g_pA[2][l][e0]);
                float4 p3 = *reinterpret_cast<const float4*>(&g_pA[3][l][e0]);
                v[0] += p2.x + p3.x; v[1] += p2.y + p3.y;
                v[2] += p2.z + p3.z; v[3] += p2.w + p3.w;
            } else {
                const float* xp = &g_Xpre[((size_t)t * 64 + b4) * 3072 + n];
#pragma unroll
                for (int c = 0; c < 4; c++) v[c] += xp[(size_t)c * 3072];
            }
#pragma unroll
            for (int c = 0; c < 4; c++) {
                int b = b4 + c;
                float rv = sigm(v[c]) * g_hbuf[rd][l][b * 1024 + nn];
                g_rhH[l][b * 1024 + nn] = __float2half_rn(rv);
            }
        }
        gridbar();

        // ---- Phase C: g rh-path (96 jobs, 1 per CTA) ----
        nv = 0;
        if (cta < 96) {
            int l = cta >> 5;
            int r = cta & 31;
            int tt8 = r >> 2, nh = (r >> 1) & 1, kq = r & 1;
            int t = w - l;
            if (t >= 0 && t < 512) {
                ja[0].A = g_WhF + ((size_t)l * 3072 + 2048 + tt8 * 128) * 1024 + kq * 512;
                ja[0].BH = g_rhH[l] + nh * 32 * 1024 + kq * 512;
                ja[0].dst = &g_pC[2 + kq][l][tt8 * 128 * 64 + nh * 32];
                nv = 1;
            }
        }
        run_jobs(ja, nv, sm0, tid, mw, nw, lane, rlo, cb);
        gridbar();

        // ---- EpiD: z + g + h update (float4 over batch) ----
        for (int idx = gtid; idx < 3 * 1024 * 16; idx += NCTA * NTHR) {
            int l = idx / (1024 * 16);
            int rem = idx - l * (1024 * 16);
            int t = w - l;
            if (t < 0 || t >= 512) continue;
            int n = rem >> 4;
            int b4 = (rem & 15) << 2;
            int e0 = n * 64 + b4;
            const float* bias = (l == 0) ? bh0 : bhr + (l - 1) * 3072;
            float bz = bias[n], bg = bias[2048 + n];
            float4 a0 = *reinterpret_cast<const float4*>(&g_pA[0][l][e0]);
            float4 a1 = *reinterpret_cast<const float4*>(&g_pA[1][l][e0]);
            float4 c2 = *reinterpret_cast<const float4*>(&g_pC[2][l][e0]);
            float4 c3 = *reinterpret_cast<const float4*>(&g_pC[3][l][e0]);
            float vz[4] = {a0.x + a1.x + bz, a0.y + a1.y + bz, a0.z + a1.z + bz,
                           a0.w + a1.w + bz};
            float vg[4] = {c2.x + c3.x + bg, c2.y + c3.y + bg, c2.z + c3.z + bg,
                           c2.w + c3.w + bg};
            if (l > 0) {
                float4 a2 = *reinterpret_cast<const float4*>(&g_pA[2][l][e0]);
                float4 a3 = *reinterpret_cast<const float4*>(&g_pA[3][l][e0]);
                float4 c0 = *reinterpret_cast<const float4*>(&g_pC[0][l][e0]);
                float4 c1 = *reinterpret_cast<const float4*>(&g_pC[1][l][e0]);
                vz[0] += a2.x + a3.x; vz[1] += a2.y + a3.y;
                vz[2] += a2.z + a3.z; vz[3] += a2.w + a3.w;
                vg[0] += c0.x + c1.x; vg[1] += c0.y + c1.y;
                vg[2] += c0.z + c1.z; vg[3] += c0.w + c1.w;
            } else {
                const float* xp = &g_Xpre[((size_t)t * 64 + b4) * 3072];
#pragma unroll
                for (int c = 0; c < 4; c++) {
                    vz[c] += xp[(size_t)c * 3072 + n];
                    vg[c] += xp[(size_t)c * 3072 + 2048 + n];
                }
            }
#pragma unroll
            for (int c = 0; c < 4; c++) {
                int b = b4 + c;
                float z = sigm(vz[c]);
                float gg = tanhf(vg[c]);
                float hp = g_hbuf[rd][l][b * 1024 + n];
                float hn = z * hp + (1.f - z) * gg;
                g_hbuf[wb][l][b * 1024 + n] = hn;
                g_hbH[wb][l][b * 1024 + n] = __float2half_rn(hn);
                if (l == 2) g_H2[((size_t)t * 64 + b) * 1024 + n] = hn;
            }
        }
        gridbar();
    }
}

__global__ __launch_bounds__(128, 2) void k_yout(const float* __restrict__ Wout,
                                                 const float* __restrict__ bout,
                                                 float* __restrict__ out) {
    __shared__ __align__(16) u64 Sm[6144];
    int s = blockIdx.x;
    gemm_tile(g_H2 + (size_t)s * 64 * 1024, 1024, Wout, 1024,
              out + (size_t)s * 128, 512 * 128, bout, 32, Sm);
}

__global__ void k_hout(float* __restrict__ out) {
    int i = blockIdx.x * 256 + threadIdx.x;
    if (i >= 3 * 64 * 1024) return;
    int l = i / (64 * 1024);
    int r = i % (64 * 1024);
    int b = r / 1024, n = r % 1024;
    out[(size_t)64 * 512 * 128 + ((size_t)b * 3 + l) * 1024 + n] = g_hbuf[l & 1][l][r];
}

extern "C" void kernel_launch(void* const* d_in, const int* in_sizes, int n_in,
                              void* d_out, int out_size) {
    const float* x = (const float*)d_in[0];
    const float* Wx0 = (const float*)d_in[1];
    const float* Wh0 = (const float*)d_in[2];
    const float* bh0 = (const float*)d_in[3];
    const float* Wxr = (const float*)d_in[4];
    const float* Whr = (const float*)d_in[5];
    const float* bhr = (const float*)d_in[6];
    const float* Wout = (const float*)d_in[7];
    const float* bout = (const float*)d_in[8];
    float* out = (float*)d_out;

    cudaFuncSetAttribute(k_gru, cudaFuncAttributeMaxDynamicSharedMemorySize, NSTAGE * BUFSZ);

    k_pad<<<1, 32>>>();
    k_conv<<<2048, 256>>>(Wh0, Whr, Wxr);
    k_xpre<<<dim3(24, 512), 128>>>(x, Wx0);
    k_gru<<<NCTA, NTHR, NSTAGE * BUFSZ>>>(bh0, bhr);  // my 4th launch -> ncu -s 5
    k_yout<<<512, 128>>>(Wout, bout, out);
    k_hout<<<(3 * 64 * 1024 + 255) / 256, 256>>>(out);
}

// round 15
// speedup vs baseline: 1.8738x; 1.0307x over previous
#include <cuda_runtime.h>
#include <cuda_fp16.h>
#include <cstddef>
#include <cstdint>

typedef unsigned long long u64;
typedef unsigned int u32;

#define NCTA 148
#define NTHR 512
#define NSTAGE 4

// smem chunk (bytes): A(fp16 W) 128x128 rows padded 272B; B act 32x128
#define OFF_BH 34816
#define BUFSZ 43520

// ---------------- device scratch ----------------
__device__ float g_Xpre[(size_t)512 * 64 * 3072];  // [t][b][3072]
__device__ float g_H2[(size_t)512 * 64 * 1024];    // [t][b][1024]
__device__ float g_hbuf[2][3][65536];              // fp32 h (parity, layer) [b][n]
__device__ __align__(16) __half g_hbH[2][3][65536];
__device__ __align__(16) __half g_rhH[3][65536];
__device__ __align__(16) __half g_WhF[(size_t)3 * 3072 * 1024];  // l0=Wh0, l1/2=Whr
__device__ __align__(16) __half g_WxF[(size_t)2 * 3072 * 1024];  // Wxr
// K-half partials, element layout [n*64 + b]
__device__ float g_pA[4][3][2048 * 64];  // zr: 0-1 h-path kq, 2-3 x-path kq
__device__ float g_pC[4][3][1024 * 64];  // g:  0-1 x-path kq, 2-3 rh-path kq
__device__ unsigned g_cnt;
__device__ volatile unsigned g_gen;

// ---------------- generic helpers ----------------
__device__ __forceinline__ u64 ffma2(u64 a, u64 b, u64 c) {
    u64 d;
    asm("fma.rn.f32x2 %0, %1, %2, %3;" : "=l"(d) : "l"(a), "l"(b), "l"(c));
    return d;
}
__device__ __forceinline__ float psum(u64 a) {
    float2 f = *reinterpret_cast<float2*>(&a);
    return f.x + f.y;
}
__device__ __forceinline__ float sigm(float x) { return 1.f / (1.f + __expf(-x)); }

__device__ __forceinline__ void gridbar() {
    __syncthreads();
    if (threadIdx.x == 0) {
        unsigned old = g_gen;
        __threadfence();
        if (atomicAdd(&g_cnt, 1u) == NCTA - 1) {
            g_cnt = 0;
            __threadfence();
            g_gen = old + 1;
        } else {
            while (g_gen == old) __nanosleep(32);
            __threadfence();
        }
    }
    __syncthreads();
}

// ---------------- mma / ldmatrix / cp.async primitives ----------------
__device__ __forceinline__ u32 smem_u32(const void* p) {
    u32 a;
    asm("{ .reg .u64 t; cvta.to.shared.u64 t, %1; cvt.u32.u64 %0, t; }" : "=r"(a) : "l"(p));
    return a;
}
__device__ __forceinline__ void mma16816(float* d, const u32* a, const u32* b) {
    asm volatile(
        "mma.sync.aligned.m16n8k16.row.col.f32.f16.f16.f32 "
        "{%0,%1,%2,%3}, {%4,%5,%6,%7}, {%8,%9}, {%0,%1,%2,%3};"
        : "+f"(d[0]), "+f"(d[1]), "+f"(d[2]), "+f"(d[3])
        : "r"(a[0]), "r"(a[1]), "r"(a[2]), "r"(a[3]), "r"(b[0]), "r"(b[1]));
}
__device__ __forceinline__ void ldm4(u32& r0, u32& r1, u32& r2, u32& r3, u32 addr) {
    asm volatile("ldmatrix.sync.aligned.m8n8.x4.shared.b16 {%0,%1,%2,%3}, [%4];"
                 : "=r"(r0), "=r"(r1), "=r"(r2), "=r"(r3) : "r"(addr));
}
__device__ __forceinline__ void cpa(u32 dst, const void* src) {
    asm volatile("cp.async.cg.shared.global [%0], [%1], 16;" :: "r"(dst), "l"(src) : "memory");
}
__device__ __forceinline__ void cp_commit() { asm volatile("cp.async.commit_group;" ::: "memory"); }
__device__ __forceinline__ void cp_waitN(int rem) {
    if (rem >= 2) asm volatile("cp.async.wait_group 2;" ::: "memory");
    else if (rem == 1) asm volatile("cp.async.wait_group 1;" ::: "memory");
    else asm volatile("cp.async.wait_group 0;" ::: "memory");
}

struct Job { const __half *A, *BH; float* dst; };

__device__ __forceinline__ Job jsel(const Job ja[3], int k) {
    Job r = ja[0];
    if (k == 1) r = ja[1];
    if (k == 2) r = ja[2];
    return r;
}

// issue one K=128 chunk (W 128x128 fp16, act 32x128 fp16) into smem buffer
__device__ __forceinline__ void issue_chunk(u32 sbuf, const Job& s, int koff, int tid) {
#pragma unroll
    for (int it = 0; it < 4; it++) {
        int idx = tid + NTHR * it;
        int row = idx >> 4, c16 = idx & 15;
        u32 d = sbuf + row * 272 + c16 * 16;
        size_t so = (size_t)row * 1024 + koff + c16 * 8;
        cpa(d, s.A + so);
    }
    {
        int row = tid >> 4, c16 = tid & 15;
        u32 d = sbuf + OFF_BH + row * 272 + c16 * 16;
        size_t so = (size_t)row * 1024 + koff + c16 * 8;
        cpa(d, s.BH + so);
    }
    cp_commit();
}

// compute one K=128 chunk: 16 warps = 8(M) x 2(N); warp tile m16 x n16
__device__ __forceinline__ void mma_chunk(u32 sbuf, float (&acc)[2][4], int mw, int nw,
                                          int lane) {
    const int arow = ((lane >> 3) & 1) * 8 + (lane & 7);
    const int akk = ((lane >> 4) & 1) * 8;
    const int brow = ((lane >> 4) & 1) * 8 + (lane & 7);
    const int bkk = ((lane >> 3) & 1) * 8;
#pragma unroll
    for (int ks = 0; ks < 8; ks++) {
        int kOff = ks * 16;
        u32 aH[4];
        {
            int row = mw * 16 + arow;
            u32 ad = sbuf + row * 272 + (kOff + akk) * 2;
            ldm4(aH[0], aH[1], aH[2], aH[3], ad);
        }
        u32 bH[2][2];
        {
            int nrow = nw * 16 + brow;
            u32 bd = sbuf + OFF_BH + nrow * 272 + (kOff + bkk) * 2;
            u32 r0, r1, r2, r3;
            ldm4(r0, r1, r2, r3, bd);
            bH[0][0] = r0; bH[0][1] = r1; bH[1][0] = r2; bH[1][1] = r3;
        }
#pragma unroll
        for (int nt = 0; nt < 2; nt++) mma16816(acc[nt], aH, bH[nt]);
    }
}

__device__ __forceinline__ void zero_acc(float (&acc)[2][4]) {
#pragma unroll
    for (int j = 0; j < 2; j++)
#pragma unroll
        for (int e = 0; e < 4; e++) acc[j][e] = 0.f;
}

// run nv jobs x 4 chunks (K=128 each), 4-stage ring, depth-3 prefetch
__device__ __forceinline__ void run_jobs(const Job ja[3], int nv, u32 sm0, int tid, int mw,
                                         int nw, int lane, int rlo, int cb) {
    if (nv == 0) return;
    float acc[2][4];
    zero_acc(acc);
    const int n = nv * 4;
#pragma unroll
    for (int j = 0; j < 3; j++)
        if (j < n) issue_chunk(sm0 + j * BUFSZ, jsel(ja, j >> 2), (j & 3) * 128, tid);
    for (int i = 0; i < n; i++) {
        int rem = n - 1 - i;
        cp_waitN(rem < 2 ? rem : 2);
        __syncthreads();
        int nx = i + 3;
        if (nx < n)
            issue_chunk(sm0 + (nx % NSTAGE) * BUFSZ, jsel(ja, nx >> 2), (nx & 3) * 128, tid);
        mma_chunk(sm0 + (i % NSTAGE) * BUFSZ, acc, mw, nw, lane);
        if ((i & 3) == 3) {
            float* dst = jsel(ja, i >> 2).dst;
#pragma unroll
            for (int half = 0; half < 2; half++) {
                int mrow = mw * 16 + half * 8 + rlo;
#pragma unroll
                for (int nt = 0; nt < 2; nt++)
#pragma unroll
                    for (int e = 0; e < 2; e++)
                        dst[mrow * 64 + nw * 16 + nt * 8 + cb + e] = acc[nt][half * 2 + e];
            }
            zero_acc(acc);
        }
    }
    __syncthreads();
}

// ---------------- SIMT f32x2 GEMM (xpre / yout) ----------------
__device__ __forceinline__ void gemm_tile(const float* __restrict__ A, int lda,
                                          const float* __restrict__ W, int ldw,
                                          float* __restrict__ C, int cld,
                                          const float* __restrict__ bias, int nch,
                                          u64* __restrict__ Sm) {
    const int tid = threadIdx.x, tx = tid & 15, ty = tid >> 4;
    u64 acc[8][8];
#pragma unroll
    for (int i = 0; i < 8; i++)
#pragma unroll
        for (int j = 0; j < 8; j++) acc[i][j] = 0ull;
    u64 rA[8], rB[16];
#pragma unroll
    for (int it = 0; it < 8; it++) {
        int idx = tid + 128 * it, row = idx >> 4, k8 = idx & 15;
        rA[it] = *reinterpret_cast<const u64*>(A + (size_t)row * lda + (k8 << 1));
    }
#pragma unroll
    for (int it = 0; it < 16; it++) {
        int idx = tid + 128 * it, row = idx >> 4, k8 = idx & 15;
        rB[it] = *reinterpret_cast<const u64*>(W + (size_t)row * ldw + (k8 << 1));
    }
    for (int c = 0; c < nch; c++) {
        u64* Ab = Sm + (c & 1) * 3072;
        u64* Bb = Ab + 1024;
#pragma unroll
        for (int it = 0; it < 8; it++) {
            int idx = tid + 128 * it, row = idx >> 4, k8 = idx & 15;
            Ab[(row << 4) + (k8 ^ ((row >> 3) & 15))] = rA[it];
        }
#pragma unroll
        for (int it = 0; it < 16; it++) {
            int idx = tid + 128 * it, row = idx >> 4, k8 = idx & 15;
            Bb[(row << 4) + (k8 ^ ((row >> 3) & 15))] = rB[it];
        }
        __syncthreads();
        if (c + 1 < nch) {
            const float* A2 = A + (c + 1) * 32;
            const float* W2 = W + (c + 1) * 32;
#pragma unroll
            for (int it = 0; it < 8; it++) {
                int idx = tid + 128 * it, row = idx >> 4, k8 = idx & 15;
                rA[it] = *reinterpret_cast<const u64*>(A2 + (size_t)row * lda + (k8 << 1));
            }
#pragma unroll
            for (int it = 0; it < 16; it++) {
                int idx = tid + 128 * it, row = idx >> 4, k8 = idx & 15;
                rB[it] = *reinterpret_cast<const u64*>(W2 + (size_t)row * ldw + (k8 << 1));
            }
        }
#pragma unroll
        for (int k8 = 0; k8 < 16; k8++) {
            u64 a2[8], b2[8];
#pragma unroll
            for (int i = 0; i < 8; i++) a2[i] = Ab[((ty * 8 + i) << 4) + (k8 ^ ty)];
#pragma unroll
            for (int j = 0; j < 8; j++) b2[j] = Bb[((tx * 8 + j) << 4) + (k8 ^ tx)];
#pragma unroll
            for (int i = 0; i < 8; i++)
#pragma unroll
                for (int j = 0; j < 8; j++) acc[i][j] = ffma2(a2[i], b2[j], acc[i][j]);
        }
    }
#pragma unroll
    for (int i = 0; i < 8; i++)
#pragma unroll
        for (int j = 0; j < 8; j++) {
            float v = psum(acc[i][j]);
            if (bias) v += bias[tx * 8 + j];
            C[(size_t)(ty * 8 + i) * cld + tx * 8 + j] = v;
        }
    __syncthreads();
}

// ---------------- kernels ----------------
__global__ void k_pad() {}

// weights fp32 -> fp16
__global__ void k_conv(const float* __restrict__ Wh0, const float* __restrict__ Whr,
                       const float* __restrict__ Wxr) {
    const size_t NWH = (size_t)3 * 3072 * 1024;
    const size_t NTOT = (size_t)5 * 3072 * 1024;
    for (size_t i = (size_t)blockIdx.x * blockDim.x + threadIdx.x; i < NTOT;
         i += (size_t)gridDim.x * blockDim.x) {
        if (i < NWH) {
            float w = (i < (size_t)3072 * 1024) ? Wh0[i] : Whr[i - (size_t)3072 * 1024];
            g_WhF[i] = __float2half_rn(w);
        } else {
            size_t o = i - NWH;
            g_WxF[o] = __float2half_rn(Wxr[o]);
        }
    }
}

__global__ __launch_bounds__(128, 2) void k_xpre(const float* __restrict__ x,
                                                 const float* __restrict__ Wx0) {
    __shared__ __align__(16) u64 Sm[6144];
    int n0 = blockIdx.x * 128, s = blockIdx.y;
    gemm_tile(x + (size_t)s * 128, 512 * 128, Wx0 + (size_t)n0 * 128, 128,
              g_Xpre + (size_t)s * 64 * 3072 + n0, 3072, nullptr, 4, Sm);
}

// persistent wavefront GRU: fp16, 1 combo, K=128 chunks, 4 barriers/wave
__global__ __launch_bounds__(NTHR) void k_gru(const float* __restrict__ bh0,
                                              const float* __restrict__ bhr) {
    extern __shared__ __align__(16) char dsm[];
    const u32 sm0 = smem_u32(dsm);
    const int tid = threadIdx.x, wid = tid >> 5, lane = tid & 31;
    const int mw = wid >> 1, nw = wid & 1;
    const int cta = blockIdx.x;
    const int gtid = cta * NTHR + tid;
    const int rlo = lane >> 2, cb = (lane & 3) * 2;

    for (int i = gtid; i < 2 * 3 * 65536; i += NCTA * NTHR) {
        (&g_hbuf[0][0][0])[i] = 0.f;
        (&g_hbH[0][0][0])[i] = __float2half_rn(0.f);
    }
    gridbar();

    for (int w = 0; w < 514; ++w) {
        const int rd = w & 1, wb = rd ^ 1;

        // ---- build Phase A jobs (once per wave) ----
        Job ja[3];
        int nv = 0;
#pragma unroll
        for (int k = 0; k < 3; k++) {
            int j = cta + k * NCTA;
            if (j >= 384) break;
            if (j < 192) {  // zr h-path
                int l = j >> 6;
                int r = j & 63;
                int tt = r >> 2, nh = (r >> 1) & 1, kq = r & 1;
                int t = w - l;
                if (t < 0 || t >= 512) continue;
                ja[nv].A = g_WhF + ((size_t)l * 3072 + tt * 128) * 1024 + kq * 512;
                ja[nv].BH = g_hbH[rd][l] + nh * 32 * 1024 + kq * 512;
                ja[nv].dst = &g_pA[kq][l][tt * 128 * 64 + nh * 32];
                nv++;
            } else if (j < 320) {  // zr x-path
                int j2 = j - 192;
                int lm = j2 >> 6;
                int r = j2 & 63;
                int tt = r >> 2, nh = (r >> 1) & 1, kq = r & 1;
                int l = lm + 1;
                int t = w - l;
                if (t < 0 || t >= 512) continue;
                ja[nv].A = g_WxF + ((size_t)lm * 3072 + tt * 128) * 1024 + kq * 512;
                ja[nv].BH = g_hbH[rd][lm] + nh * 32 * 1024 + kq * 512;
                ja[nv].dst = &g_pA[2 + kq][l][tt * 128 * 64 + nh * 32];
                nv++;
            } else {  // g x-path
                int j3 = j - 320;
                int lm = j3 >> 5;
                int r = j3 & 31;
                int tt8 = r >> 2, nh = (r >> 1) & 1, kq = r & 1;
                int l = lm + 1;
                int t = w - l;
                if (t < 0 || t >= 512) continue;
                ja[nv].A = g_WxF + ((size_t)lm * 3072 + 2048 + tt8 * 128) * 1024 + kq * 512;
                ja[nv].BH = g_hbH[rd][lm] + nh * 32 * 1024 + kq * 512;
                ja[nv].dst = &g_pC[kq][l][tt8 * 128 * 64 + nh * 32];
                nv++;
            }
        }
        run_jobs(ja, nv, sm0, tid, mw, nw, lane, rlo, cb);
        gridbar();

        // ---- EpiB: rh only (float4 over batch) ----
        for (int idx = gtid; idx < 3 * 1024 * 16; idx += NCTA * NTHR) {
            int l = idx / (1024 * 16);
            int rem = idx - l * (1024 * 16);
            int t = w - l;
            if (t < 0 || t >= 512) continue;
            int nn = rem >> 4;
            int b4 = (rem & 15) << 2;
            int n = 1024 + nn;
            int e0 = n * 64 + b4;
            float4 p0 = *reinterpret_cast<const float4*>(&g_pA[0][l][e0]);
            float4 p1 = *reinterpret_cast<const float4*>(&g_pA[1][l][e0]);
            float bv = (l == 0) ? bh0[n] : bhr[(l - 1) * 3072 + n];
            float v[4] = {p0.x + p1.x + bv, p0.y + p1.y + bv, p0.z + p1.z + bv,
                          p0.w + p1.w + bv};
            if (l > 0) {
                float4 p2 = *reinterpret_cast<const float4*>(&g_pA[2][l][e0]);
                float4 p3 = *reinterpret_cast<const float4*>(&g_pA[3][l][e0]);
                v[0] += p2.x + p3.x; v[1] += p2.y + p3.y;
                v[2] += p2.z + p3.z; v[3] += p2.w + p3.w;
            } else {
                const float* xp = &g_Xpre[((size_t)t * 64 + b4) * 3072 + n];
#pragma unroll
                for (int c = 0; c < 4; c++) v[c] += xp[(size_t)c * 3072];
            }
#pragma unroll
            for (int c = 0; c < 4; c++) {
                int b = b4 + c;
                float rv = sigm(v[c]) * g_hbuf[rd][l][b * 1024 + nn];
                g_rhH[l][b * 1024 + nn] = __float2half_rn(rv);
            }
        }
        gridbar();

        // ---- Phase C: g rh-path (96 jobs, 1 per CTA) ----
        nv = 0;
        if (cta < 96) {
            int l = cta >> 5;
            int r = cta & 31;
            int tt8 = r >> 2, nh = (r >> 1) & 1, kq = r & 1;
            int t = w - l;
            if (t >= 0 && t < 512) {
                ja[0].A = g_WhF + ((size_t)l * 3072 + 2048 + tt8 * 128) * 1024 + kq * 512;
                ja[0].BH = g_rhH[l] + nh * 32 * 1024 + kq * 512;
                ja[0].dst = &g_pC[2 + kq][l][tt8 * 128 * 64 + nh * 32];
                nv = 1;
            }
        }
        run_jobs(ja, nv, sm0, tid, mw, nw, lane, rlo, cb);
        gridbar();

        // ---- EpiD: z + g + h update (float4 over batch) ----
        for (int idx = gtid; idx < 3 * 1024 * 16; idx += NCTA * NTHR) {
            int l = idx / (1024 * 16);
            int rem = idx - l * (1024 * 16);
            int t = w - l;
            if (t < 0 || t >= 512) continue;
            int n = rem >> 4;
            int b4 = (rem & 15) << 2;
            int e0 = n * 64 + b4;
            const float* bias = (l == 0) ? bh0 : bhr + (l - 1) * 3072;
            float bz = bias[n], bg = bias[2048 + n];
            float4 a0 = *reinterpret_cast<const float4*>(&g_pA[0][l][e0]);
            float4 a1 = *reinterpret_cast<const float4*>(&g_pA[1][l][e0]);
            float4 c2 = *reinterpret_cast<const float4*>(&g_pC[2][l][e0]);
            float4 c3 = *reinterpret_cast<const float4*>(&g_pC[3][l][e0]);
            float vz[4] = {a0.x + a1.x + bz, a0.y + a1.y + bz, a0.z + a1.z + bz,
                           a0.w + a1.w + bz};
            float vg[4] = {c2.x + c3.x + bg, c2.y + c3.y + bg, c2.z + c3.z + bg,
                           c2.w + c3.w + bg};
            if (l > 0) {
                float4 a2 = *reinterpret_cast<const float4*>(&g_pA[2][l][e0]);
                float4 a3 = *reinterpret_cast<const float4*>(&g_pA[3][l][e0]);
                float4 c0 = *reinterpret_cast<const float4*>(&g_pC[0][l][e0]);
                float4 c1 = *reinterpret_cast<const float4*>(&g_pC[1][l][e0]);
                vz[0] += a2.x + a3.x; vz[1] += a2.y + a3.y;
                vz[2] += a2.z + a3.z; vz[3] += a2.w + a3.w;
                vg[0] += c0.x + c1.x; vg[1] += c0.y + c1.y;
                vg[2] += c0.z + c1.z; vg[3] += c0.w + c1.w;
            } else {
                const float* xp = &g_Xpre[((size_t)t * 64 + b4) * 3072];
#pragma unroll
                for (int c = 0; c < 4; c++) {
                    vz[c] += xp[(size_t)c * 3072 + n];
                    vg[c] += xp[(size_t)c * 3072 + 2048 + n];
                }
            }
#pragma unroll
            for (int c = 0; c < 4; c++) {
                int b = b4 + c;
                float z = sigm(vz[c]);
                float gg = tanhf(vg[c]);
                float hp = g_hbuf[rd][l][b * 1024 + n];
                float hn = z * hp + (1.f - z) * gg;
                g_hbuf[wb][l][b * 1024 + n] = hn;
                g_hbH[wb][l][b * 1024 + n] = __float2half_rn(hn);
                if (l == 2) g_H2[((size_t)t * 64 + b) * 1024 + n] = hn;
            }
        }
        gridbar();
    }
}

__global__ __launch_bounds__(128, 2) void k_yout(const float* __restrict__ Wout,
                                                 const float* __restrict__ bout,
                                                 float* __restrict__ out) {
    __shared__ __align__(16) u64 Sm[6144];
    int s = blockIdx.x;
    gemm_tile(g_H2 + (size_t)s * 64 * 1024, 1024, Wout, 1024,
              out + (size_t)s * 128, 512 * 128, bout, 32, Sm);
}

__global__ void k_hout(float* __restrict__ out) {
    int i = blockIdx.x * 256 + threadIdx.x;
    if (i >= 3 * 64 * 1024) return;
    int l = i / (64 * 1024);
    int r = i % (64 * 1024);
    int b = r / 1024, n = r % 1024;
    out[(size_t)64 * 512 * 128 + ((size_t)b * 3 + l) * 1024 + n] = g_hbuf[l & 1][l][r];
}

extern "C" void kernel_launch(void* const* d_in, const int* in_sizes, int n_in,
                              void* d_out, int out_size) {
    const float* x = (const float*)d_in[0];
    const float* Wx0 = (const float*)d_in[1];
    const float* Wh0 = (const float*)d_in[2];
    const float* bh0 = (const float*)d_in[3];
    const float* Wxr = (const float*)d_in[4];
    const float* Whr = (const float*)d_in[5];
    const float* bhr = (const float*)d_in[6];
    const float* Wout = (const float*)d_in[7];
    const float* bout = (const float*)d_in[8];
    float* out = (float*)d_out;

    cudaFuncSetAttribute(k_gru, cudaFuncAttributeMaxDynamicSharedMemorySize, NSTAGE * BUFSZ);

    k_pad<<<1, 32>>>();
    k_conv<<<2048, 256>>>(Wh0, Whr, Wxr);
    k_xpre<<<dim3(24, 512), 128>>>(x, Wx0);
    k_gru<<<NCTA, NTHR, NSTAGE * BUFSZ>>>(bh0, bhr);  // my 4th launch -> ncu -s 5
    k_yout<<<512, 128>>>(Wout, bout, out);
    k_hout<<<(3 * 64 * 1024 + 255) / 256, 256>>>(out);
}